// round 9
// baseline (speedup 1.0000x reference)
#include <cuda_runtime.h>
#include <cuda_bf16.h>
#include <cstdint>
#include <math.h>

#define NNODES 50000
#define NEDGES 800000
#define FDIM   256
#define NCLS   40
#define SCAN_BLOCKS ((NNODES + 1023) / 1024)

// -------- scratch --------
__device__ float g_bufA[(size_t)NNODES * FDIM];
__device__ float g_bufB[(size_t)NNODES * FDIM];
__device__ float g_P[(size_t)NNODES * NCLS];
__device__ unsigned g_W1h[256 * 128], g_W1l[256 * 128];   // [n][kpair] packed bf16x2
__device__ unsigned g_W2h[256 * 128], g_W2l[256 * 128];
__device__ int   g_deg[NNODES];
__device__ int   g_off[NNODES];
__device__ int   g_rowptr[NNODES + 1];
__device__ int   g_col[NEDGES];
__device__ int   g_bsum[SCAN_BLOCKS];
__device__ int   g_not64 = 0;

// -------- bf16 split helpers --------
__device__ __forceinline__ void split2(float x0, float x1, unsigned& hi, unsigned& lo) {
    __nv_bfloat16 h0 = __float2bfloat16_rn(x0);
    __nv_bfloat16 h1 = __float2bfloat16_rn(x1);
    float r0 = x0 - __bfloat162float(h0);
    float r1 = x1 - __bfloat162float(h1);
    __nv_bfloat162 hp(h0, h1);
    __nv_bfloat162 lp(__float2bfloat16_rn(r0), __float2bfloat16_rn(r1));
    hi = *reinterpret_cast<unsigned*>(&hp);
    lo = *reinterpret_cast<unsigned*>(&lp);
}

// -------- W prep --------
__global__ void prepW_kernel(const float* __restrict__ W1, const float* __restrict__ W2) {
    int t = blockIdx.x * blockDim.x + threadIdx.x;
    if (t >= 2 * 256 * 128) return;
    int which = t >> 15;
    int i = t & 32767;
    int n = i >> 7, kp = i & 127;
    const float* W = which ? W2 : W1;
    float x0 = __ldg(&W[(2 * kp) * 256 + n]);
    float x1 = __ldg(&W[(2 * kp + 1) * 256 + n]);
    unsigned hi, lo;
    split2(x0, x1, hi, lo);
    if (which) { g_W2h[n * 128 + kp] = hi; g_W2l[n * 128 + kp] = lo; }
    else       { g_W1h[n * 128 + kp] = hi; g_W1l[n * 128 + kp] = lo; }
}

// -------- setup + dtype detect --------
__global__ void setup_kernel(const void* __restrict__ ei) {
    int i = blockIdx.x * blockDim.x + threadIdx.x;
    if (i < NNODES) { g_deg[i] = 0; g_off[i] = 0; }
    if (blockIdx.x == 0 && threadIdx.x < 256) {
        const int* w = (const int*)ei;
        if (w[2 * threadIdx.x + 1] != 0) atomicOr(&g_not64, 1);
    }
}

__device__ __forceinline__ int edge_at(const void* ei, int idx) {
    if (g_not64 == 0) return (int)((const long long*)ei)[idx];
    return ((const int*)ei)[idx];
}

__global__ void count_deg_kernel(const void* __restrict__ ei) {
    int e = blockIdx.x * blockDim.x + threadIdx.x;
    if (e < NEDGES) {
        int d = edge_at(ei, NEDGES + e);
        if ((unsigned)d < NNODES) atomicAdd(&g_deg[d], 1);
    }
}

// -------- multiblock scan --------
__global__ void scan_phaseA() {
    int i = blockIdx.x * 1024 + threadIdx.x;
    int v = (i < NNODES) ? g_deg[i] : 0;
    int s = v;
#pragma unroll
    for (int o = 16; o > 0; o >>= 1) s += __shfl_xor_sync(0xFFFFFFFFu, s, o);
    __shared__ int ws[32];
    int w = threadIdx.x >> 5, l = threadIdx.x & 31;
    if (l == 0) ws[w] = s;
    __syncthreads();
    if (w == 0) {
        int t = ws[l];
#pragma unroll
        for (int o = 16; o > 0; o >>= 1) t += __shfl_xor_sync(0xFFFFFFFFu, t, o);
        if (l == 0) g_bsum[blockIdx.x] = t;
    }
}

__global__ void scan_phaseC() {
    int i = blockIdx.x * 1024 + threadIdx.x;
    int v = (i < NNODES) ? g_deg[i] : 0;
    int w = threadIdx.x >> 5, l = threadIdx.x & 31;
    int x = v;
#pragma unroll
    for (int o = 1; o < 32; o <<= 1) {
        int y = __shfl_up_sync(0xFFFFFFFFu, x, o);
        if (l >= o) x += y;
    }
    __shared__ int wtot[32];
    __shared__ int sboff;
    if (l == 31) wtot[w] = x;
    __syncthreads();
    if (w == 0) {
        int s = 0;
        for (int b = l; b < blockIdx.x; b += 32) s += g_bsum[b];
#pragma unroll
        for (int o = 16; o > 0; o >>= 1) s += __shfl_xor_sync(0xFFFFFFFFu, s, o);
        if (l == 0) sboff = s;
        int t = wtot[l];
#pragma unroll
        for (int o = 1; o < 32; o <<= 1) {
            int y = __shfl_up_sync(0xFFFFFFFFu, t, o);
            if (l >= o) t += y;
        }
        wtot[l] = t;
    }
    __syncthreads();
    int woff = (w > 0) ? wtot[w - 1] : 0;
    int excl = sboff + woff + x - v;
    if (i < NNODES) g_rowptr[i] = excl;
    if (i == NNODES - 1) g_rowptr[NNODES] = excl + v;
}

__global__ void fill_kernel(const void* __restrict__ ei) {
    int e = blockIdx.x * blockDim.x + threadIdx.x;
    if (e < NEDGES) {
        int s = edge_at(ei, e);
        int d = edge_at(ei, NEDGES + e);
        if ((unsigned)s < NNODES && (unsigned)d < NNODES) {
            int pos = g_rowptr[d] + atomicAdd(&g_off[d], 1);
            if ((unsigned)pos < NEDGES) g_col[pos] = s;
        }
    }
}

// -------- agg (bufB -> bufA) with fused bias + relu --------
__global__ void aggBR_kernel(const float* __restrict__ bias) {
    int t = blockIdx.x * blockDim.x + threadIdx.x;
    int v = t >> 6;
    int f = t & 63;
    if (v >= NNODES) return;
    const float4* in = (const float4*)g_bufB;
    int s = __ldg(&g_rowptr[v]);
    int e = __ldg(&g_rowptr[v + 1]);
    float4 a0 = make_float4(0.f, 0.f, 0.f, 0.f);
    float4 a1 = a0, a2 = a0, a3 = a0;
    int j = s;
    for (; j + 4 <= e; j += 4) {
        int c0 = __ldg(&g_col[j]);
        int c1 = __ldg(&g_col[j + 1]);
        int c2 = __ldg(&g_col[j + 2]);
        int c3 = __ldg(&g_col[j + 3]);
        float4 x0 = __ldg(&in[(size_t)c0 * 64 + f]);
        float4 x1 = __ldg(&in[(size_t)c1 * 64 + f]);
        float4 x2 = __ldg(&in[(size_t)c2 * 64 + f]);
        float4 x3 = __ldg(&in[(size_t)c3 * 64 + f]);
        a0.x += x0.x; a0.y += x0.y; a0.z += x0.z; a0.w += x0.w;
        a1.x += x1.x; a1.y += x1.y; a1.z += x1.z; a1.w += x1.w;
        a2.x += x2.x; a2.y += x2.y; a2.z += x2.z; a2.w += x2.w;
        a3.x += x3.x; a3.y += x3.y; a3.z += x3.z; a3.w += x3.w;
    }
    for (; j < e; j++) {
        int c = __ldg(&g_col[j]);
        float4 x = __ldg(&in[(size_t)c * 64 + f]);
        a0.x += x.x; a0.y += x.y; a0.z += x.z; a0.w += x.w;
    }
    float4 b = __ldg(&((const float4*)bias)[f]);
    float4 r;
    r.x = fmaxf((a0.x + a1.x) + (a2.x + a3.x) + b.x, 0.f);
    r.y = fmaxf((a0.y + a1.y) + (a2.y + a3.y) + b.y, 0.f);
    r.z = fmaxf((a0.z + a1.z) + (a2.z + a3.z) + b.z, 0.f);
    r.w = fmaxf((a0.w + a1.w) + (a2.w + a3.w) + b.w, 0.f);
    ((float4*)g_bufA)[(size_t)v * 64 + f] = r;
}

// -------- bf16x3 GEMM: A via smem+ldmatrix, B fragments direct from gmem --------
// Block 64x128, 8 warps (2m x 4n), warp tile 32x32, k-step 16, m16n8k16 bf16 MMA.
#define MMA_BF16(d, a, b) \
    asm volatile("mma.sync.aligned.m16n8k16.row.col.f32.bf16.bf16.f32 " \
        "{%0,%1,%2,%3}, {%4,%5,%6,%7}, {%8,%9}, {%0,%1,%2,%3};" \
        : "+f"(d[0]), "+f"(d[1]), "+f"(d[2]), "+f"(d[3]) \
        : "r"(a[0]), "r"(a[1]), "r"(a[2]), "r"(a[3]), "r"(b[0]), "r"(b[1]))

#define LDSM4(r0, r1, r2, r3, addr) \
    asm volatile("ldmatrix.sync.aligned.m8n8.x4.shared.b16 {%0,%1,%2,%3}, [%4];" \
        : "=r"(r0), "=r"(r1), "=r"(r2), "=r"(r3) : "r"(addr))

#define A_BUF_BYTES (64 * 12 * 4)

template<int LAYER>
__global__ void __launch_bounds__(256, 2)
gemm_bf16_kernel(const float* __restrict__ Aext, int M) {
    __shared__ unsigned sAh[2][64][12], sAl[2][64][12];     // [buf][m][kpair] (8 of 12 used)
    const float* A = (LAYER == 1) ? Aext : g_bufA;
    const unsigned* Wh = (LAYER == 1) ? g_W1h : g_W2h;
    const unsigned* Wl = (LAYER == 1) ? g_W1l : g_W2l;

    const int m0 = blockIdx.x * 64;
    const int n0 = blockIdx.y * 128;
    const int tid = threadIdx.x;
    const int warp = tid >> 5, lane = tid & 31;
    const int wm = warp >> 2, wn = warp & 3;     // 2 x 4 warps
    const int g = lane >> 2, l = lane & 3;

    // A smem writers
    const int ar = tid >> 2;            // A row 0..63
    const int ac = (tid & 3) * 4;       // A k element offset
    const int akp = ac >> 1;            // pair offset 0/2/4/6

    // ldmatrix source addresses (buffer 0)
    const int a_row = wm * 32 + (lane & 15);
    const int a_col = (lane >> 4) * 4;
    const unsigned aAh = (unsigned)__cvta_generic_to_shared(&sAh[0][a_row][a_col]);
    const unsigned aAl = (unsigned)__cvta_generic_to_shared(&sAl[0][a_row][a_col]);

    // B fragment gmem pointers: bh[j][h] = Wh[(n0+wn*32+j*8+g)*128 + kt*8 + l + h*4]
    const unsigned* whp = Wh + (size_t)(n0 + wn * 32 + g) * 128 + l;
    const unsigned* wlp = Wl + (size_t)(n0 + wn * 32 + g) * 128 + l;

    float acc[2][4][4];
#pragma unroll
    for (int i = 0; i < 2; i++)
#pragma unroll
        for (int j = 0; j < 4; j++)
#pragma unroll
            for (int q = 0; q < 4; q++) acc[i][j][q] = 0.f;

    const bool aval = (m0 + ar) < M;
    const float* Arow = A + (size_t)(m0 + ar) * 256;

    float4 fa = make_float4(0.f, 0.f, 0.f, 0.f);
    if (aval) fa = *(const float4*)&Arow[ac];

    unsigned bh[2][4][2], bl[2][4][2];   // [parity][j][half]
#pragma unroll
    for (int j = 0; j < 4; j++) {
        bh[0][j][0] = __ldg(&whp[j * 1024]);
        bh[0][j][1] = __ldg(&whp[j * 1024 + 4]);
        bl[0][j][0] = __ldg(&wlp[j * 1024]);
        bl[0][j][1] = __ldg(&wlp[j * 1024 + 4]);
    }

    int p = 0;
#pragma unroll 2
    for (int kt = 0; kt < 16; kt++) {
        const int par = kt & 1;
        // write prefetched A tile into buffer p
        {
            uint2 h, lo;
            split2(fa.x, fa.y, h.x, lo.x);
            split2(fa.z, fa.w, h.y, lo.y);
            *(uint2*)&sAh[p][ar][akp] = h;
            *(uint2*)&sAl[p][ar][akp] = lo;
        }
        __syncthreads();
        // prefetch next k-step
        if (kt < 15) {
            int k = (kt + 1) * 16;
            fa = make_float4(0.f, 0.f, 0.f, 0.f);
            if (aval) fa = *(const float4*)&Arow[k + ac];
            const unsigned* whn = whp + (kt + 1) * 8;
            const unsigned* wln = wlp + (kt + 1) * 8;
#pragma unroll
            for (int j = 0; j < 4; j++) {
                bh[par ^ 1][j][0] = __ldg(&whn[j * 1024]);
                bh[par ^ 1][j][1] = __ldg(&whn[j * 1024 + 4]);
                bl[par ^ 1][j][0] = __ldg(&wln[j * 1024]);
                bl[par ^ 1][j][1] = __ldg(&wln[j * 1024 + 4]);
            }
        }
        // A fragment loads via ldmatrix
        const unsigned offA = (unsigned)(p * A_BUF_BYTES);
        unsigned ah[2][4], al_[2][4];
        LDSM4(ah[0][0], ah[0][1], ah[0][2], ah[0][3], aAh + offA);
        LDSM4(ah[1][0], ah[1][1], ah[1][2], ah[1][3], aAh + offA + 16 * 48);
        LDSM4(al_[0][0], al_[0][1], al_[0][2], al_[0][3], aAl + offA);
        LDSM4(al_[1][0], al_[1][1], al_[1][2], al_[1][3], aAl + offA + 16 * 48);
#pragma unroll
        for (int i = 0; i < 2; i++)
#pragma unroll
            for (int j = 0; j < 4; j++) {
                MMA_BF16(acc[i][j], ah[i], bh[par][j]);
                MMA_BF16(acc[i][j], ah[i], bl[par][j]);
                MMA_BF16(acc[i][j], al_[i], bh[par][j]);
            }
        p ^= 1;
    }

#pragma unroll
    for (int i = 0; i < 2; i++) {
        int row0 = m0 + wm * 32 + i * 16 + g;
        int row1 = row0 + 8;
#pragma unroll
        for (int j = 0; j < 4; j++) {
            int col = n0 + wn * 32 + j * 8 + 2 * l;
            if (row0 < M) {
                float2 v = {acc[i][j][0], acc[i][j][1]};
                *(float2*)&g_bufB[(size_t)row0 * 256 + col] = v;
            }
            if (row1 < M) {
                float2 v = {acc[i][j][2], acc[i][j][3]};
                *(float2*)&g_bufB[(size_t)row1 * 256 + col] = v;
            }
        }
    }
}

// -------- layer-3 projection: g_P = g_bufA @ W3 (no bias) --------
__global__ void __launch_bounds__(256, 2)
gemm3_kernel(const float* __restrict__ W3, int M) {
    __shared__ float sW[256][40];
    __shared__ __align__(16) float sA[64][128];
    const int m0 = blockIdx.x * 128;
    const int tid = threadIdx.x;
    const int rt = tid >> 3;
    const int ct = tid & 7;

    for (int i = tid; i < 256 * 40; i += 256) sW[i / 40][i % 40] = __ldg(&W3[i]);

    float acc[4][5];
#pragma unroll
    for (int i = 0; i < 4; i++)
#pragma unroll
        for (int j = 0; j < 5; j++) acc[i][j] = 0.f;

    const int ar = tid >> 1;
    const int akb = (tid & 1) * 4;

    for (int k0 = 0; k0 < 256; k0 += 64) {
        __syncthreads();
#pragma unroll
        for (int pass = 0; pass < 8; pass++) {
            int ak = akb + pass * 8;
            float4 av = make_float4(0.f, 0.f, 0.f, 0.f);
            if (m0 + ar < M) av = *(const float4*)&g_bufA[(size_t)(m0 + ar) * 256 + k0 + ak];
            sA[ak + 0][ar] = av.x;
            sA[ak + 1][ar] = av.y;
            sA[ak + 2][ar] = av.z;
            sA[ak + 3][ar] = av.w;
        }
        __syncthreads();
        for (int kk = 0; kk < 64; kk++) {
            float4 a4 = *(const float4*)&sA[kk][rt * 4];
            float a[4] = {a4.x, a4.y, a4.z, a4.w};
            const float* wrow = &sW[k0 + kk][ct * 5];
            float w0 = wrow[0], w1 = wrow[1], w2 = wrow[2], w3 = wrow[3], w4 = wrow[4];
#pragma unroll
            for (int i = 0; i < 4; i++) {
                acc[i][0] += a[i] * w0;
                acc[i][1] += a[i] * w1;
                acc[i][2] += a[i] * w2;
                acc[i][3] += a[i] * w3;
                acc[i][4] += a[i] * w4;
            }
        }
    }

#pragma unroll
    for (int i = 0; i < 4; i++) {
        int row = m0 + rt * 4 + i;
        if (row < M) {
#pragma unroll
            for (int j = 0; j < 5; j++)
                g_P[(size_t)row * NCLS + ct * 5 + j] = acc[i][j];
        }
    }
}

// -------- final: out[v] = log_softmax( agg(P)[v] + b3 ); warp per node --------
__global__ void aggout_kernel(const float* __restrict__ b3, float* __restrict__ out, int M) {
    int warp = (blockIdx.x * blockDim.x + threadIdx.x) >> 5;
    int lane = threadIdx.x & 31;
    if (warp >= M) return;
    int s = __ldg(&g_rowptr[warp]);
    int e = __ldg(&g_rowptr[warp + 1]);
    bool act = lane < 20;
    int c0 = lane, c1 = lane + 20;
    float acc0 = 0.f, acc1 = 0.f;
    for (int j = s; j < e; j++) {
        int c = __ldg(&g_col[j]);
        const float* pr = &g_P[(size_t)c * NCLS];
        if (act) {
            acc0 += pr[c0];
            acc1 += pr[c1];
        }
    }
    float v0 = act ? acc0 + __ldg(&b3[c0]) : -INFINITY;
    float v1 = act ? acc1 + __ldg(&b3[c1]) : -INFINITY;
    float m = fmaxf(v0, v1);
#pragma unroll
    for (int o = 16; o > 0; o >>= 1) m = fmaxf(m, __shfl_xor_sync(0xFFFFFFFFu, m, o));
    float ssum = act ? (expf(v0 - m) + expf(v1 - m)) : 0.f;
#pragma unroll
    for (int o = 16; o > 0; o >>= 1) ssum += __shfl_xor_sync(0xFFFFFFFFu, ssum, o);
    float ls = logf(ssum);
    if (act) {
        out[(size_t)warp * NCLS + c0] = v0 - m - ls;
        out[(size_t)warp * NCLS + c1] = v1 - m - ls;
    }
}

__global__ void tail_kernel(float* out, int start, int total, float val) {
    int i = start + blockIdx.x * blockDim.x + threadIdx.x;
    if (i < total) out[i] = val;
}

extern "C" void kernel_launch(void* const* d_in, const int* in_sizes, int n_in,
                              void* d_out, int out_size) {
    const float* features = (const float*)d_in[0];
    const void*  ei       = d_in[1];
    const float* W1 = (const float*)d_in[4];
    const float* b1 = (const float*)d_in[5];
    const float* W2 = (const float*)d_in[6];
    const float* b2 = (const float*)d_in[7];
    const float* W3 = (const float*)d_in[8];
    const float* b3 = (const float*)d_in[9];
    float* out = (float*)d_out;

    const int N = NNODES, E = NEDGES;
    dim3 ggrid((N + 63) / 64, 2);

    prepW_kernel<<<(2 * 256 * 128 + 255) / 256, 256>>>(W1, W2);   // 0
    setup_kernel<<<(N + 255) / 256, 256>>>(ei);                   // 1
    count_deg_kernel<<<(E + 255) / 256, 256>>>(ei);               // 2
    gemm_bf16_kernel<1><<<ggrid, 256>>>(features, N);             // 3  T1 = X@W1 (ncu target)
    scan_phaseA<<<SCAN_BLOCKS, 1024>>>();                         // 4
    scan_phaseC<<<SCAN_BLOCKS, 1024>>>();                         // 5
    fill_kernel<<<(E + 255) / 256, 256>>>(ei);                    // 6
    aggBR_kernel<<<(N * 64 + 255) / 256, 256>>>(b1);              // 7  H1 = relu(agg(T1)+b1)
    gemm_bf16_kernel<2><<<ggrid, 256>>>(nullptr, N);              // 8  T2 = H1@W2
    aggBR_kernel<<<(N * 64 + 255) / 256, 256>>>(b2);              // 9  H2 = relu(agg(T2)+b2)
    gemm3_kernel<<<(N + 127) / 128, 256>>>(W3, N);                // 10 P = H2@W3
    aggout_kernel<<<(N * 32 + 255) / 256, 256>>>(b3, out, N);     // 11

    int NC = N * NCLS;
    if (out_size > NC) {
        int extra = out_size - NC;
        tail_kernel<<<(extra + 255) / 256, 256>>>(out, NC, out_size, (float)(3 * N));
    }
}

// round 11
// speedup vs baseline: 1.2969x; 1.2969x over previous
#include <cuda_runtime.h>
#include <cuda_bf16.h>
#include <cuda_fp16.h>
#include <cstdint>
#include <math.h>

#define NNODES 50000
#define NEDGES 800000
#define FDIM   256
#define NCLS   40
#define SCAN_BLOCKS ((NNODES + 1023) / 1024)

// -------- scratch --------
__device__ float  g_bufA[(size_t)NNODES * FDIM];          // H (post-agg, fp32)
__device__ __half g_bufT[(size_t)(NNODES + 64) * FDIM];   // T = A@W (pre-agg, fp16)
__device__ float  g_P[(size_t)NNODES * NCLS];
__device__ unsigned g_W1h[256 * 128], g_W1l[256 * 128];   // [n][kpair] packed bf16x2
__device__ unsigned g_W2h[256 * 128], g_W2l[256 * 128];
__device__ int   g_deg[NNODES];
__device__ int   g_off[NNODES];
__device__ int   g_rowptr[NNODES + 1];
__device__ int   g_col[NEDGES];
__device__ int   g_bsum[SCAN_BLOCKS];
__device__ int   g_not64 = 0;

// -------- bf16 split helpers --------
__device__ __forceinline__ void split2(float x0, float x1, unsigned& hi, unsigned& lo) {
    __nv_bfloat16 h0 = __float2bfloat16_rn(x0);
    __nv_bfloat16 h1 = __float2bfloat16_rn(x1);
    float r0 = x0 - __bfloat162float(h0);
    float r1 = x1 - __bfloat162float(h1);
    __nv_bfloat162 hp(h0, h1);
    __nv_bfloat162 lp(__float2bfloat16_rn(r0), __float2bfloat16_rn(r1));
    hi = *reinterpret_cast<unsigned*>(&hp);
    lo = *reinterpret_cast<unsigned*>(&lp);
}

// -------- W prep --------
__global__ void prepW_kernel(const float* __restrict__ W1, const float* __restrict__ W2) {
    int t = blockIdx.x * blockDim.x + threadIdx.x;
    if (t >= 2 * 256 * 128) return;
    int which = t >> 15;
    int i = t & 32767;
    int n = i >> 7, kp = i & 127;
    const float* W = which ? W2 : W1;
    float x0 = __ldg(&W[(2 * kp) * 256 + n]);
    float x1 = __ldg(&W[(2 * kp + 1) * 256 + n]);
    unsigned hi, lo;
    split2(x0, x1, hi, lo);
    if (which) { g_W2h[n * 128 + kp] = hi; g_W2l[n * 128 + kp] = lo; }
    else       { g_W1h[n * 128 + kp] = hi; g_W1l[n * 128 + kp] = lo; }
}

// -------- setup + dtype detect --------
__global__ void setup_kernel(const void* __restrict__ ei) {
    int i = blockIdx.x * blockDim.x + threadIdx.x;
    if (i < NNODES) { g_deg[i] = 0; g_off[i] = 0; }
    if (blockIdx.x == 0 && threadIdx.x < 256) {
        const int* w = (const int*)ei;
        if (w[2 * threadIdx.x + 1] != 0) atomicOr(&g_not64, 1);
    }
}

__device__ __forceinline__ int edge_at(const void* ei, int idx) {
    if (g_not64 == 0) return (int)((const long long*)ei)[idx];
    return ((const int*)ei)[idx];
}

__global__ void count_deg_kernel(const void* __restrict__ ei) {
    int e = blockIdx.x * blockDim.x + threadIdx.x;
    if (e < NEDGES) {
        int d = edge_at(ei, NEDGES + e);
        if ((unsigned)d < NNODES) atomicAdd(&g_deg[d], 1);
    }
}

// -------- multiblock scan --------
__global__ void scan_phaseA() {
    int i = blockIdx.x * 1024 + threadIdx.x;
    int v = (i < NNODES) ? g_deg[i] : 0;
    int s = v;
#pragma unroll
    for (int o = 16; o > 0; o >>= 1) s += __shfl_xor_sync(0xFFFFFFFFu, s, o);
    __shared__ int ws[32];
    int w = threadIdx.x >> 5, l = threadIdx.x & 31;
    if (l == 0) ws[w] = s;
    __syncthreads();
    if (w == 0) {
        int t = ws[l];
#pragma unroll
        for (int o = 16; o > 0; o >>= 1) t += __shfl_xor_sync(0xFFFFFFFFu, t, o);
        if (l == 0) g_bsum[blockIdx.x] = t;
    }
}

__global__ void scan_phaseC() {
    int i = blockIdx.x * 1024 + threadIdx.x;
    int v = (i < NNODES) ? g_deg[i] : 0;
    int w = threadIdx.x >> 5, l = threadIdx.x & 31;
    int x = v;
#pragma unroll
    for (int o = 1; o < 32; o <<= 1) {
        int y = __shfl_up_sync(0xFFFFFFFFu, x, o);
        if (l >= o) x += y;
    }
    __shared__ int wtot[32];
    __shared__ int sboff;
    if (l == 31) wtot[w] = x;
    __syncthreads();
    if (w == 0) {
        int s = 0;
        for (int b = l; b < blockIdx.x; b += 32) s += g_bsum[b];
#pragma unroll
        for (int o = 16; o > 0; o >>= 1) s += __shfl_xor_sync(0xFFFFFFFFu, s, o);
        if (l == 0) sboff = s;
        int t = wtot[l];
#pragma unroll
        for (int o = 1; o < 32; o <<= 1) {
            int y = __shfl_up_sync(0xFFFFFFFFu, t, o);
            if (l >= o) t += y;
        }
        wtot[l] = t;
    }
    __syncthreads();
    int woff = (w > 0) ? wtot[w - 1] : 0;
    int excl = sboff + woff + x - v;
    if (i < NNODES) g_rowptr[i] = excl;
    if (i == NNODES - 1) g_rowptr[NNODES] = excl + v;
}

__global__ void fill_kernel(const void* __restrict__ ei) {
    int e = blockIdx.x * blockDim.x + threadIdx.x;
    if (e < NEDGES) {
        int s = edge_at(ei, e);
        int d = edge_at(ei, NEDGES + e);
        if ((unsigned)s < NNODES && (unsigned)d < NNODES) {
            int pos = g_rowptr[d] + atomicAdd(&g_off[d], 1);
            if ((unsigned)pos < NEDGES) g_col[pos] = s;
        }
    }
}

// -------- agg (g_bufT fp16 -> g_bufA fp32) with fused bias + relu --------
// 64 threads/node, each handles 4 features (one 8B uint2 = 4 halves).
__global__ void aggBR_kernel(const float* __restrict__ bias) {
    int t = blockIdx.x * blockDim.x + threadIdx.x;
    int v = t >> 6;
    int f = t & 63;
    if (v >= NNODES) return;
    const uint2* in = (const uint2*)g_bufT;
    int s = __ldg(&g_rowptr[v]);
    int e = __ldg(&g_rowptr[v + 1]);
    float4 a0 = make_float4(0.f, 0.f, 0.f, 0.f);
    float4 a1 = a0, a2 = a0, a3 = a0;
    int j = s;
    for (; j + 4 <= e; j += 4) {
        int c0 = __ldg(&g_col[j]);
        int c1 = __ldg(&g_col[j + 1]);
        int c2 = __ldg(&g_col[j + 2]);
        int c3 = __ldg(&g_col[j + 3]);
        uint2 x0 = __ldg(&in[(size_t)c0 * 64 + f]);
        uint2 x1 = __ldg(&in[(size_t)c1 * 64 + f]);
        uint2 x2 = __ldg(&in[(size_t)c2 * 64 + f]);
        uint2 x3 = __ldg(&in[(size_t)c3 * 64 + f]);
        float2 p, q;
        p = __half22float2(*(__half2*)&x0.x); q = __half22float2(*(__half2*)&x0.y);
        a0.x += p.x; a0.y += p.y; a0.z += q.x; a0.w += q.y;
        p = __half22float2(*(__half2*)&x1.x); q = __half22float2(*(__half2*)&x1.y);
        a1.x += p.x; a1.y += p.y; a1.z += q.x; a1.w += q.y;
        p = __half22float2(*(__half2*)&x2.x); q = __half22float2(*(__half2*)&x2.y);
        a2.x += p.x; a2.y += p.y; a2.z += q.x; a2.w += q.y;
        p = __half22float2(*(__half2*)&x3.x); q = __half22float2(*(__half2*)&x3.y);
        a3.x += p.x; a3.y += p.y; a3.z += q.x; a3.w += q.y;
    }
    for (; j < e; j++) {
        int c = __ldg(&g_col[j]);
        uint2 x = __ldg(&in[(size_t)c * 64 + f]);
        float2 p = __half22float2(*(__half2*)&x.x);
        float2 q = __half22float2(*(__half2*)&x.y);
        a0.x += p.x; a0.y += p.y; a0.z += q.x; a0.w += q.y;
    }
    float4 b = __ldg(&((const float4*)bias)[f]);
    float4 r;
    r.x = fmaxf((a0.x + a1.x) + (a2.x + a3.x) + b.x, 0.f);
    r.y = fmaxf((a0.y + a1.y) + (a2.y + a3.y) + b.y, 0.f);
    r.z = fmaxf((a0.z + a1.z) + (a2.z + a3.z) + b.z, 0.f);
    r.w = fmaxf((a0.w + a1.w) + (a2.w + a3.w) + b.w, 0.f);
    ((float4*)g_bufA)[(size_t)v * 64 + f] = r;
}

// -------- bf16x3 GEMM with ldmatrix + double-buffered smem (R8-proven) --------
// Block 64x128, 8 warps (2m x 4n), warp tile 32x32, k-step 16, m16n8k16 bf16 MMA.
// Output stored as fp16 into g_bufT.
#define MMA_BF16(d, a, b) \
    asm volatile("mma.sync.aligned.m16n8k16.row.col.f32.bf16.bf16.f32 " \
        "{%0,%1,%2,%3}, {%4,%5,%6,%7}, {%8,%9}, {%0,%1,%2,%3};" \
        : "+f"(d[0]), "+f"(d[1]), "+f"(d[2]), "+f"(d[3]) \
        : "r"(a[0]), "r"(a[1]), "r"(a[2]), "r"(a[3]), "r"(b[0]), "r"(b[1]))

#define LDSM4(r0, r1, r2, r3, addr) \
    asm volatile("ldmatrix.sync.aligned.m8n8.x4.shared.b16 {%0,%1,%2,%3}, [%4];" \
        : "=r"(r0), "=r"(r1), "=r"(r2), "=r"(r3) : "r"(addr))

#define A_BUF_BYTES (64 * 12 * 4)
#define B_BUF_BYTES (128 * 12 * 4)

template<int LAYER>
__global__ void __launch_bounds__(256, 2)
gemm_bf16_kernel(const float* __restrict__ Aext, int M) {
    __shared__ unsigned sAh[2][64][12], sAl[2][64][12];     // [buf][m][kpair] (8 of 12 used)
    __shared__ unsigned sBh[2][128][12], sBl[2][128][12];   // [buf][n][kpair]
    const float* A = (LAYER == 1) ? Aext : g_bufA;
    const unsigned* Wh = (LAYER == 1) ? g_W1h : g_W2h;
    const unsigned* Wl = (LAYER == 1) ? g_W1l : g_W2l;

    const int m0 = blockIdx.x * 64;
    const int n0 = blockIdx.y * 128;
    const int tid = threadIdx.x;
    const int warp = tid >> 5, lane = tid & 31;
    const int wm = warp >> 2, wn = warp & 3;     // 2 x 4 warps
    const int g = lane >> 2, l = lane & 3;

    // smem writers
    const int ar = tid >> 2;            // A row 0..63
    const int ac = (tid & 3) * 4;       // A k element offset
    const int akp = ac >> 1;            // pair offset 0/2/4/6
    const int bn = tid >> 1;            // B n row 0..127
    const int bq = (tid & 1) * 4;       // B kpair offset 0/4

    // ldmatrix source addresses (buffer 0)
    const int a_row = wm * 32 + (lane & 15);
    const int a_col = (lane >> 4) * 4;
    const int b_row = wn * 32 + ((lane >> 4) << 3) + (lane & 7);
    const int b_col = ((lane >> 3) & 1) * 4;
    const unsigned aAh = (unsigned)__cvta_generic_to_shared(&sAh[0][a_row][a_col]);
    const unsigned aAl = (unsigned)__cvta_generic_to_shared(&sAl[0][a_row][a_col]);
    const unsigned aBh = (unsigned)__cvta_generic_to_shared(&sBh[0][b_row][b_col]);
    const unsigned aBl = (unsigned)__cvta_generic_to_shared(&sBl[0][b_row][b_col]);

    float acc[2][4][4];
#pragma unroll
    for (int i = 0; i < 2; i++)
#pragma unroll
        for (int j = 0; j < 4; j++)
#pragma unroll
            for (int q = 0; q < 4; q++) acc[i][j][q] = 0.f;

    const bool aval = (m0 + ar) < M;
    const float* Arow = A + (size_t)(m0 + ar) * 256;
    const unsigned* WhRow = Wh + (size_t)(n0 + bn) * 128;
    const unsigned* WlRow = Wl + (size_t)(n0 + bn) * 128;

    float4 fa = make_float4(0.f, 0.f, 0.f, 0.f);
    if (aval) fa = *(const float4*)&Arow[ac];
    uint4 wh = *(const uint4*)&WhRow[bq];
    uint4 wl = *(const uint4*)&WlRow[bq];

    int p = 0;
#pragma unroll 1
    for (int kt = 0; kt < 16; kt++) {
        // write prefetched tile into buffer p
        {
            uint2 h, lo;
            split2(fa.x, fa.y, h.x, lo.x);
            split2(fa.z, fa.w, h.y, lo.y);
            *(uint2*)&sAh[p][ar][akp] = h;
            *(uint2*)&sAl[p][ar][akp] = lo;
        }
        *(uint4*)&sBh[p][bn][bq] = wh;
        *(uint4*)&sBl[p][bn][bq] = wl;
        __syncthreads();
        // prefetch next k-step from gmem
        if (kt < 15) {
            int k = (kt + 1) * 16;
            fa = make_float4(0.f, 0.f, 0.f, 0.f);
            if (aval) fa = *(const float4*)&Arow[k + ac];
            wh = *(const uint4*)&WhRow[(kt + 1) * 8 + bq];
            wl = *(const uint4*)&WlRow[(kt + 1) * 8 + bq];
        }
        // fragment loads via ldmatrix
        const unsigned offA = (unsigned)(p * A_BUF_BYTES);
        const unsigned offB = (unsigned)(p * B_BUF_BYTES);
        unsigned ah[2][4], al_[2][4], bh[4][2], bl_[4][2];
        LDSM4(ah[0][0], ah[0][1], ah[0][2], ah[0][3], aAh + offA);
        LDSM4(ah[1][0], ah[1][1], ah[1][2], ah[1][3], aAh + offA + 16 * 48);
        LDSM4(al_[0][0], al_[0][1], al_[0][2], al_[0][3], aAl + offA);
        LDSM4(al_[1][0], al_[1][1], al_[1][2], al_[1][3], aAl + offA + 16 * 48);
        LDSM4(bh[0][0], bh[0][1], bh[1][0], bh[1][1], aBh + offB);
        LDSM4(bh[2][0], bh[2][1], bh[3][0], bh[3][1], aBh + offB + 16 * 48);
        LDSM4(bl_[0][0], bl_[0][1], bl_[1][0], bl_[1][1], aBl + offB);
        LDSM4(bl_[2][0], bl_[2][1], bl_[3][0], bl_[3][1], aBl + offB + 16 * 48);
#pragma unroll
        for (int i = 0; i < 2; i++)
#pragma unroll
            for (int j = 0; j < 4; j++) {
                MMA_BF16(acc[i][j], ah[i], bh[j]);
                MMA_BF16(acc[i][j], ah[i], bl_[j]);
                MMA_BF16(acc[i][j], al_[i], bh[j]);
            }
        p ^= 1;
    }

    // epilogue: fp16 stores into g_bufT
#pragma unroll
    for (int i = 0; i < 2; i++) {
        int row0 = m0 + wm * 32 + i * 16 + g;
        int row1 = row0 + 8;
#pragma unroll
        for (int j = 0; j < 4; j++) {
            int col = n0 + wn * 32 + j * 8 + 2 * l;
            if (row0 < M) {
                __half2 v = __floats2half2_rn(acc[i][j][0], acc[i][j][1]);
                *(__half2*)&g_bufT[(size_t)row0 * 256 + col] = v;
            }
            if (row1 < M) {
                __half2 v = __floats2half2_rn(acc[i][j][2], acc[i][j][3]);
                *(__half2*)&g_bufT[(size_t)row1 * 256 + col] = v;
            }
        }
    }
}

// -------- layer-3 projection: g_P = g_bufA @ W3 (no bias) --------
__global__ void __launch_bounds__(256, 2)
gemm3_kernel(const float* __restrict__ W3, int M) {
    __shared__ float sW[256][40];
    __shared__ __align__(16) float sA[64][128];
    const int m0 = blockIdx.x * 128;
    const int tid = threadIdx.x;
    const int rt = tid >> 3;
    const int ct = tid & 7;

    for (int i = tid; i < 256 * 40; i += 256) sW[i / 40][i % 40] = __ldg(&W3[i]);

    float acc[4][5];
#pragma unroll
    for (int i = 0; i < 4; i++)
#pragma unroll
        for (int j = 0; j < 5; j++) acc[i][j] = 0.f;

    const int ar = tid >> 1;
    const int akb = (tid & 1) * 4;

    for (int k0 = 0; k0 < 256; k0 += 64) {
        __syncthreads();
#pragma unroll
        for (int pass = 0; pass < 8; pass++) {
            int ak = akb + pass * 8;
            float4 av = make_float4(0.f, 0.f, 0.f, 0.f);
            if (m0 + ar < M) av = *(const float4*)&g_bufA[(size_t)(m0 + ar) * 256 + k0 + ak];
            sA[ak + 0][ar] = av.x;
            sA[ak + 1][ar] = av.y;
            sA[ak + 2][ar] = av.z;
            sA[ak + 3][ar] = av.w;
        }
        __syncthreads();
        for (int kk = 0; kk < 64; kk++) {
            float4 a4 = *(const float4*)&sA[kk][rt * 4];
            float a[4] = {a4.x, a4.y, a4.z, a4.w};
            const float* wrow = &sW[k0 + kk][ct * 5];
            float w0 = wrow[0], w1 = wrow[1], w2 = wrow[2], w3 = wrow[3], w4 = wrow[4];
#pragma unroll
            for (int i = 0; i < 4; i++) {
                acc[i][0] += a[i] * w0;
                acc[i][1] += a[i] * w1;
                acc[i][2] += a[i] * w2;
                acc[i][3] += a[i] * w3;
                acc[i][4] += a[i] * w4;
            }
        }
    }

#pragma unroll
    for (int i = 0; i < 4; i++) {
        int row = m0 + rt * 4 + i;
        if (row < M) {
#pragma unroll
            for (int j = 0; j < 5; j++)
                g_P[(size_t)row * NCLS + ct * 5 + j] = acc[i][j];
        }
    }
}

// -------- final: out[v] = log_softmax( agg(P)[v] + b3 ); warp per node --------
__global__ void aggout_kernel(const float* __restrict__ b3, float* __restrict__ out, int M) {
    int warp = (blockIdx.x * blockDim.x + threadIdx.x) >> 5;
    int lane = threadIdx.x & 31;
    if (warp >= M) return;
    int s = __ldg(&g_rowptr[warp]);
    int e = __ldg(&g_rowptr[warp + 1]);
    bool act = lane < 20;
    int c0 = lane, c1 = lane + 20;
    float acc0 = 0.f, acc1 = 0.f;
    for (int j = s; j < e; j++) {
        int c = __ldg(&g_col[j]);
        const float* pr = &g_P[(size_t)c * NCLS];
        if (act) {
            acc0 += pr[c0];
            acc1 += pr[c1];
        }
    }
    float v0 = act ? acc0 + __ldg(&b3[c0]) : -INFINITY;
    float v1 = act ? acc1 + __ldg(&b3[c1]) : -INFINITY;
    float m = fmaxf(v0, v1);
#pragma unroll
    for (int o = 16; o > 0; o >>= 1) m = fmaxf(m, __shfl_xor_sync(0xFFFFFFFFu, m, o));
    float ssum = act ? (expf(v0 - m) + expf(v1 - m)) : 0.f;
#pragma unroll
    for (int o = 16; o > 0; o >>= 1) ssum += __shfl_xor_sync(0xFFFFFFFFu, ssum, o);
    float ls = logf(ssum);
    if (act) {
        out[(size_t)warp * NCLS + c0] = v0 - m - ls;
        out[(size_t)warp * NCLS + c1] = v1 - m - ls;
    }
}

__global__ void tail_kernel(float* out, int start, int total, float val) {
    int i = start + blockIdx.x * blockDim.x + threadIdx.x;
    if (i < total) out[i] = val;
}

extern "C" void kernel_launch(void* const* d_in, const int* in_sizes, int n_in,
                              void* d_out, int out_size) {
    const float* features = (const float*)d_in[0];
    const void*  ei       = d_in[1];
    const float* W1 = (const float*)d_in[4];
    const float* b1 = (const float*)d_in[5];
    const float* W2 = (const float*)d_in[6];
    const float* b2 = (const float*)d_in[7];
    const float* W3 = (const float*)d_in[8];
    const float* b3 = (const float*)d_in[9];
    float* out = (float*)d_out;

    const int N = NNODES, E = NEDGES;
    dim3 ggrid((N + 63) / 64, 2);

    prepW_kernel<<<(2 * 256 * 128 + 255) / 256, 256>>>(W1, W2);   // 0
    setup_kernel<<<(N + 255) / 256, 256>>>(ei);                   // 1
    count_deg_kernel<<<(E + 255) / 256, 256>>>(ei);               // 2
    gemm_bf16_kernel<1><<<ggrid, 256>>>(features, N);             // 3  T1 = X@W1 (ncu target)
    scan_phaseA<<<SCAN_BLOCKS, 1024>>>();                         // 4
    scan_phaseC<<<SCAN_BLOCKS, 1024>>>();                         // 5
    fill_kernel<<<(E + 255) / 256, 256>>>(ei);                    // 6
    aggBR_kernel<<<(N * 64 + 255) / 256, 256>>>(b1);              // 7  H1 = relu(agg(T1)+b1)
    gemm_bf16_kernel<2><<<ggrid, 256>>>(nullptr, N);              // 8  T2 = H1@W2
    aggBR_kernel<<<(N * 64 + 255) / 256, 256>>>(b2);              // 9  H2 = relu(agg(T2)+b2)
    gemm3_kernel<<<(N + 127) / 128, 256>>>(W3, N);                // 10 P = H2@W3
    aggout_kernel<<<(N * 32 + 255) / 256, 256>>>(b3, out, N);     // 11

    int NC = N * NCLS;
    if (out_size > NC) {
        int extra = out_size - NC;
        tail_kernel<<<(extra + 255) / 256, 256>>>(out, NC, out_size, (float)(3 * N));
    }
}

// round 12
// speedup vs baseline: 1.3511x; 1.0417x over previous
#include <cuda_runtime.h>
#include <cuda_bf16.h>
#include <cuda_fp16.h>
#include <cstdint>
#include <math.h>

#define NNODES 50000
#define NEDGES 800000
#define FDIM   256
#define NCLS   40
#define SCAN_BLOCKS ((NNODES + 1023) / 1024)

// -------- scratch --------
__device__ float  g_bufA[(size_t)NNODES * FDIM];          // H (post-agg, fp32)
__device__ __half g_bufT[(size_t)(NNODES + 64) * FDIM];   // T = A@W (pre-agg, fp16)
__device__ float  g_P[(size_t)NNODES * NCLS];
__device__ unsigned g_W1h[256 * 128], g_W1l[256 * 128];   // [n][kpair] packed bf16x2
__device__ unsigned g_W2h[256 * 128], g_W2l[256 * 128];
__device__ int   g_deg[NNODES];
__device__ int   g_off[NNODES];
__device__ int   g_rowptr[NNODES + 1];
__device__ int   g_col[NEDGES];
__device__ int   g_bsum[SCAN_BLOCKS];
__device__ int   g_not64 = 0;

// -------- bf16 split helpers --------
__device__ __forceinline__ void split2(float x0, float x1, unsigned& hi, unsigned& lo) {
    __nv_bfloat16 h0 = __float2bfloat16_rn(x0);
    __nv_bfloat16 h1 = __float2bfloat16_rn(x1);
    float r0 = x0 - __bfloat162float(h0);
    float r1 = x1 - __bfloat162float(h1);
    __nv_bfloat162 hp(h0, h1);
    __nv_bfloat162 lp(__float2bfloat16_rn(r0), __float2bfloat16_rn(r1));
    hi = *reinterpret_cast<unsigned*>(&hp);
    lo = *reinterpret_cast<unsigned*>(&lp);
}

// -------- W prep --------
__global__ void prepW_kernel(const float* __restrict__ W1, const float* __restrict__ W2) {
    int t = blockIdx.x * blockDim.x + threadIdx.x;
    if (t >= 2 * 256 * 128) return;
    int which = t >> 15;
    int i = t & 32767;
    int n = i >> 7, kp = i & 127;
    const float* W = which ? W2 : W1;
    float x0 = __ldg(&W[(2 * kp) * 256 + n]);
    float x1 = __ldg(&W[(2 * kp + 1) * 256 + n]);
    unsigned hi, lo;
    split2(x0, x1, hi, lo);
    if (which) { g_W2h[n * 128 + kp] = hi; g_W2l[n * 128 + kp] = lo; }
    else       { g_W1h[n * 128 + kp] = hi; g_W1l[n * 128 + kp] = lo; }
}

// -------- setup + dtype detect --------
__global__ void setup_kernel(const void* __restrict__ ei) {
    int i = blockIdx.x * blockDim.x + threadIdx.x;
    if (i < NNODES) { g_deg[i] = 0; g_off[i] = 0; }
    if (blockIdx.x == 0 && threadIdx.x < 256) {
        const int* w = (const int*)ei;
        if (w[2 * threadIdx.x + 1] != 0) atomicOr(&g_not64, 1);
    }
}

__device__ __forceinline__ int edge_at(const void* ei, int idx) {
    if (g_not64 == 0) return (int)((const long long*)ei)[idx];
    return ((const int*)ei)[idx];
}

__global__ void count_deg_kernel(const void* __restrict__ ei) {
    int e = blockIdx.x * blockDim.x + threadIdx.x;
    if (e < NEDGES) {
        int d = edge_at(ei, NEDGES + e);
        if ((unsigned)d < NNODES) atomicAdd(&g_deg[d], 1);
    }
}

// -------- multiblock scan --------
__global__ void scan_phaseA() {
    int i = blockIdx.x * 1024 + threadIdx.x;
    int v = (i < NNODES) ? g_deg[i] : 0;
    int s = v;
#pragma unroll
    for (int o = 16; o > 0; o >>= 1) s += __shfl_xor_sync(0xFFFFFFFFu, s, o);
    __shared__ int ws[32];
    int w = threadIdx.x >> 5, l = threadIdx.x & 31;
    if (l == 0) ws[w] = s;
    __syncthreads();
    if (w == 0) {
        int t = ws[l];
#pragma unroll
        for (int o = 16; o > 0; o >>= 1) t += __shfl_xor_sync(0xFFFFFFFFu, t, o);
        if (l == 0) g_bsum[blockIdx.x] = t;
    }
}

__global__ void scan_phaseC() {
    int i = blockIdx.x * 1024 + threadIdx.x;
    int v = (i < NNODES) ? g_deg[i] : 0;
    int w = threadIdx.x >> 5, l = threadIdx.x & 31;
    int x = v;
#pragma unroll
    for (int o = 1; o < 32; o <<= 1) {
        int y = __shfl_up_sync(0xFFFFFFFFu, x, o);
        if (l >= o) x += y;
    }
    __shared__ int wtot[32];
    __shared__ int sboff;
    if (l == 31) wtot[w] = x;
    __syncthreads();
    if (w == 0) {
        int s = 0;
        for (int b = l; b < blockIdx.x; b += 32) s += g_bsum[b];
#pragma unroll
        for (int o = 16; o > 0; o >>= 1) s += __shfl_xor_sync(0xFFFFFFFFu, s, o);
        if (l == 0) sboff = s;
        int t = wtot[l];
#pragma unroll
        for (int o = 1; o < 32; o <<= 1) {
            int y = __shfl_up_sync(0xFFFFFFFFu, t, o);
            if (l >= o) t += y;
        }
        wtot[l] = t;
    }
    __syncthreads();
    int woff = (w > 0) ? wtot[w - 1] : 0;
    int excl = sboff + woff + x - v;
    if (i < NNODES) g_rowptr[i] = excl;
    if (i == NNODES - 1) g_rowptr[NNODES] = excl + v;
}

__global__ void fill_kernel(const void* __restrict__ ei) {
    int e = blockIdx.x * blockDim.x + threadIdx.x;
    if (e < NEDGES) {
        int s = edge_at(ei, e);
        int d = edge_at(ei, NEDGES + e);
        if ((unsigned)s < NNODES && (unsigned)d < NNODES) {
            int pos = g_rowptr[d] + atomicAdd(&g_off[d], 1);
            if ((unsigned)pos < NEDGES) g_col[pos] = s;
        }
    }
}

// -------- agg (g_bufT fp16 -> g_bufA fp32) with fused bias + relu --------
__global__ void aggBR_kernel(const float* __restrict__ bias) {
    int t = blockIdx.x * blockDim.x + threadIdx.x;
    int v = t >> 6;
    int f = t & 63;
    if (v >= NNODES) return;
    const uint2* in = (const uint2*)g_bufT;
    int s = __ldg(&g_rowptr[v]);
    int e = __ldg(&g_rowptr[v + 1]);
    float4 a0 = make_float4(0.f, 0.f, 0.f, 0.f);
    float4 a1 = a0, a2 = a0, a3 = a0;
    int j = s;
    for (; j + 4 <= e; j += 4) {
        int c0 = __ldg(&g_col[j]);
        int c1 = __ldg(&g_col[j + 1]);
        int c2 = __ldg(&g_col[j + 2]);
        int c3 = __ldg(&g_col[j + 3]);
        uint2 x0 = __ldg(&in[(size_t)c0 * 64 + f]);
        uint2 x1 = __ldg(&in[(size_t)c1 * 64 + f]);
        uint2 x2 = __ldg(&in[(size_t)c2 * 64 + f]);
        uint2 x3 = __ldg(&in[(size_t)c3 * 64 + f]);
        float2 p, q;
        p = __half22float2(*(__half2*)&x0.x); q = __half22float2(*(__half2*)&x0.y);
        a0.x += p.x; a0.y += p.y; a0.z += q.x; a0.w += q.y;
        p = __half22float2(*(__half2*)&x1.x); q = __half22float2(*(__half2*)&x1.y);
        a1.x += p.x; a1.y += p.y; a1.z += q.x; a1.w += q.y;
        p = __half22float2(*(__half2*)&x2.x); q = __half22float2(*(__half2*)&x2.y);
        a2.x += p.x; a2.y += p.y; a2.z += q.x; a2.w += q.y;
        p = __half22float2(*(__half2*)&x3.x); q = __half22float2(*(__half2*)&x3.y);
        a3.x += p.x; a3.y += p.y; a3.z += q.x; a3.w += q.y;
    }
    for (; j < e; j++) {
        int c = __ldg(&g_col[j]);
        uint2 x = __ldg(&in[(size_t)c * 64 + f]);
        float2 p = __half22float2(*(__half2*)&x.x);
        float2 q = __half22float2(*(__half2*)&x.y);
        a0.x += p.x; a0.y += p.y; a0.z += q.x; a0.w += q.y;
    }
    float4 b = __ldg(&((const float4*)bias)[f]);
    float4 r;
    r.x = fmaxf((a0.x + a1.x) + (a2.x + a3.x) + b.x, 0.f);
    r.y = fmaxf((a0.y + a1.y) + (a2.y + a3.y) + b.y, 0.f);
    r.z = fmaxf((a0.z + a1.z) + (a2.z + a3.z) + b.z, 0.f);
    r.w = fmaxf((a0.w + a1.w) + (a2.w + a3.w) + b.w, 0.f);
    ((float4*)g_bufA)[(size_t)v * 64 + f] = r;
}

// -------- bf16x3 GEMM with ldmatrix + double-buffered smem --------
#define MMA_BF16(d, a, b) \
    asm volatile("mma.sync.aligned.m16n8k16.row.col.f32.bf16.bf16.f32 " \
        "{%0,%1,%2,%3}, {%4,%5,%6,%7}, {%8,%9}, {%0,%1,%2,%3};" \
        : "+f"(d[0]), "+f"(d[1]), "+f"(d[2]), "+f"(d[3]) \
        : "r"(a[0]), "r"(a[1]), "r"(a[2]), "r"(a[3]), "r"(b[0]), "r"(b[1]))

#define LDSM4(r0, r1, r2, r3, addr) \
    asm volatile("ldmatrix.sync.aligned.m8n8.x4.shared.b16 {%0,%1,%2,%3}, [%4];" \
        : "=r"(r0), "=r"(r1), "=r"(r2), "=r"(r3) : "r"(addr))

#define A_BUF_BYTES (64 * 12 * 4)
#define B_BUF_BYTES (128 * 12 * 4)

template<int LAYER>
__global__ void __launch_bounds__(256, 2)
gemm_bf16_kernel(const float* __restrict__ Aext, int M) {
    __shared__ unsigned sAh[2][64][12], sAl[2][64][12];
    __shared__ unsigned sBh[2][128][12], sBl[2][128][12];
    const float* A = (LAYER == 1) ? Aext : g_bufA;
    const unsigned* Wh = (LAYER == 1) ? g_W1h : g_W2h;
    const unsigned* Wl = (LAYER == 1) ? g_W1l : g_W2l;

    const int m0 = blockIdx.x * 64;
    const int n0 = blockIdx.y * 128;
    const int tid = threadIdx.x;
    const int warp = tid >> 5, lane = tid & 31;
    const int wm = warp >> 2, wn = warp & 3;
    const int g = lane >> 2, l = lane & 3;

    const int ar = tid >> 2;
    const int ac = (tid & 3) * 4;
    const int akp = ac >> 1;
    const int bn = tid >> 1;
    const int bq = (tid & 1) * 4;

    const int a_row = wm * 32 + (lane & 15);
    const int a_col = (lane >> 4) * 4;
    const int b_row = wn * 32 + ((lane >> 4) << 3) + (lane & 7);
    const int b_col = ((lane >> 3) & 1) * 4;
    const unsigned aAh = (unsigned)__cvta_generic_to_shared(&sAh[0][a_row][a_col]);
    const unsigned aAl = (unsigned)__cvta_generic_to_shared(&sAl[0][a_row][a_col]);
    const unsigned aBh = (unsigned)__cvta_generic_to_shared(&sBh[0][b_row][b_col]);
    const unsigned aBl = (unsigned)__cvta_generic_to_shared(&sBl[0][b_row][b_col]);

    float acc[2][4][4];
#pragma unroll
    for (int i = 0; i < 2; i++)
#pragma unroll
        for (int j = 0; j < 4; j++)
#pragma unroll
            for (int q = 0; q < 4; q++) acc[i][j][q] = 0.f;

    const bool aval = (m0 + ar) < M;
    const float* Arow = A + (size_t)(m0 + ar) * 256;
    const unsigned* WhRow = Wh + (size_t)(n0 + bn) * 128;
    const unsigned* WlRow = Wl + (size_t)(n0 + bn) * 128;

    float4 fa = make_float4(0.f, 0.f, 0.f, 0.f);
    if (aval) fa = *(const float4*)&Arow[ac];
    uint4 wh = *(const uint4*)&WhRow[bq];
    uint4 wl = *(const uint4*)&WlRow[bq];

    int p = 0;
#pragma unroll 1
    for (int kt = 0; kt < 16; kt++) {
        {
            uint2 h, lo;
            split2(fa.x, fa.y, h.x, lo.x);
            split2(fa.z, fa.w, h.y, lo.y);
            *(uint2*)&sAh[p][ar][akp] = h;
            *(uint2*)&sAl[p][ar][akp] = lo;
        }
        *(uint4*)&sBh[p][bn][bq] = wh;
        *(uint4*)&sBl[p][bn][bq] = wl;
        __syncthreads();
        if (kt < 15) {
            int k = (kt + 1) * 16;
            fa = make_float4(0.f, 0.f, 0.f, 0.f);
            if (aval) fa = *(const float4*)&Arow[k + ac];
            wh = *(const uint4*)&WhRow[(kt + 1) * 8 + bq];
            wl = *(const uint4*)&WlRow[(kt + 1) * 8 + bq];
        }
        const unsigned offA = (unsigned)(p * A_BUF_BYTES);
        const unsigned offB = (unsigned)(p * B_BUF_BYTES);
        unsigned ah[2][4], al_[2][4], bh[4][2], bl_[4][2];
        LDSM4(ah[0][0], ah[0][1], ah[0][2], ah[0][3], aAh + offA);
        LDSM4(ah[1][0], ah[1][1], ah[1][2], ah[1][3], aAh + offA + 16 * 48);
        LDSM4(al_[0][0], al_[0][1], al_[0][2], al_[0][3], aAl + offA);
        LDSM4(al_[1][0], al_[1][1], al_[1][2], al_[1][3], aAl + offA + 16 * 48);
        LDSM4(bh[0][0], bh[0][1], bh[1][0], bh[1][1], aBh + offB);
        LDSM4(bh[2][0], bh[2][1], bh[3][0], bh[3][1], aBh + offB + 16 * 48);
        LDSM4(bl_[0][0], bl_[0][1], bl_[1][0], bl_[1][1], aBl + offB);
        LDSM4(bl_[2][0], bl_[2][1], bl_[3][0], bl_[3][1], aBl + offB + 16 * 48);
#pragma unroll
        for (int i = 0; i < 2; i++)
#pragma unroll
            for (int j = 0; j < 4; j++) {
                MMA_BF16(acc[i][j], ah[i], bh[j]);
                MMA_BF16(acc[i][j], ah[i], bl_[j]);
                MMA_BF16(acc[i][j], al_[i], bh[j]);
            }
        p ^= 1;
    }

#pragma unroll
    for (int i = 0; i < 2; i++) {
        int row0 = m0 + wm * 32 + i * 16 + g;
        int row1 = row0 + 8;
#pragma unroll
        for (int j = 0; j < 4; j++) {
            int col = n0 + wn * 32 + j * 8 + 2 * l;
            if (row0 < M) {
                __half2 v = __floats2half2_rn(acc[i][j][0], acc[i][j][1]);
                *(__half2*)&g_bufT[(size_t)row0 * 256 + col] = v;
            }
            if (row1 < M) {
                __half2 v = __floats2half2_rn(acc[i][j][2], acc[i][j][3]);
                *(__half2*)&g_bufT[(size_t)row1 * 256 + col] = v;
            }
        }
    }
}

// -------- layer-3 projection: g_P = g_bufA @ W3 (no bias) --------
__global__ void __launch_bounds__(256, 2)
gemm3_kernel(const float* __restrict__ W3, int M) {
    __shared__ float sW[256][40];
    __shared__ __align__(16) float sA[64][128];
    const int m0 = blockIdx.x * 128;
    const int tid = threadIdx.x;
    const int rt = tid >> 3;
    const int ct = tid & 7;

    for (int i = tid; i < 256 * 40; i += 256) sW[i / 40][i % 40] = __ldg(&W3[i]);

    float acc[4][5];
#pragma unroll
    for (int i = 0; i < 4; i++)
#pragma unroll
        for (int j = 0; j < 5; j++) acc[i][j] = 0.f;

    const int ar = tid >> 1;
    const int akb = (tid & 1) * 4;

    for (int k0 = 0; k0 < 256; k0 += 64) {
        __syncthreads();
#pragma unroll
        for (int pass = 0; pass < 8; pass++) {
            int ak = akb + pass * 8;
            float4 av = make_float4(0.f, 0.f, 0.f, 0.f);
            if (m0 + ar < M) av = *(const float4*)&g_bufA[(size_t)(m0 + ar) * 256 + k0 + ak];
            sA[ak + 0][ar] = av.x;
            sA[ak + 1][ar] = av.y;
            sA[ak + 2][ar] = av.z;
            sA[ak + 3][ar] = av.w;
        }
        __syncthreads();
        for (int kk = 0; kk < 64; kk++) {
            float4 a4 = *(const float4*)&sA[kk][rt * 4];
            float a[4] = {a4.x, a4.y, a4.z, a4.w};
            const float* wrow = &sW[k0 + kk][ct * 5];
            float w0 = wrow[0], w1 = wrow[1], w2 = wrow[2], w3 = wrow[3], w4 = wrow[4];
#pragma unroll
            for (int i = 0; i < 4; i++) {
                acc[i][0] += a[i] * w0;
                acc[i][1] += a[i] * w1;
                acc[i][2] += a[i] * w2;
                acc[i][3] += a[i] * w3;
                acc[i][4] += a[i] * w4;
            }
        }
    }

#pragma unroll
    for (int i = 0; i < 4; i++) {
        int row = m0 + rt * 4 + i;
        if (row < M) {
#pragma unroll
            for (int j = 0; j < 5; j++)
                g_P[(size_t)row * NCLS + ct * 5 + j] = acc[i][j];
        }
    }
}

// -------- final: out[v] = log_softmax( agg(P)[v] + b3 ); warp per node --------
__global__ void aggout_kernel(const float* __restrict__ b3, float* __restrict__ out, int M) {
    int warp = (blockIdx.x * blockDim.x + threadIdx.x) >> 5;
    int lane = threadIdx.x & 31;
    if (warp >= M) return;
    int s = __ldg(&g_rowptr[warp]);
    int e = __ldg(&g_rowptr[warp + 1]);
    bool act = lane < 20;
    int c0 = lane, c1 = lane + 20;
    float acc0 = 0.f, acc1 = 0.f;
    for (int j = s; j < e; j++) {
        int c = __ldg(&g_col[j]);
        const float* pr = &g_P[(size_t)c * NCLS];
        if (act) {
            acc0 += pr[c0];
            acc1 += pr[c1];
        }
    }
    float v0 = act ? acc0 + __ldg(&b3[c0]) : -INFINITY;
    float v1 = act ? acc1 + __ldg(&b3[c1]) : -INFINITY;
    float m = fmaxf(v0, v1);
#pragma unroll
    for (int o = 16; o > 0; o >>= 1) m = fmaxf(m, __shfl_xor_sync(0xFFFFFFFFu, m, o));
    float ssum = act ? (expf(v0 - m) + expf(v1 - m)) : 0.f;
#pragma unroll
    for (int o = 16; o > 0; o >>= 1) ssum += __shfl_xor_sync(0xFFFFFFFFu, ssum, o);
    float ls = logf(ssum);
    if (act) {
        out[(size_t)warp * NCLS + c0] = v0 - m - ls;
        out[(size_t)warp * NCLS + c1] = v1 - m - ls;
    }
}

__global__ void tail_kernel(float* out, int start, int total, float val) {
    int i = start + blockIdx.x * blockDim.x + threadIdx.x;
    if (i < total) out[i] = val;
}

extern "C" void kernel_launch(void* const* d_in, const int* in_sizes, int n_in,
                              void* d_out, int out_size) {
    const float* features = (const float*)d_in[0];
    const void*  ei       = d_in[1];
    const float* W1 = (const float*)d_in[4];
    const float* b1 = (const float*)d_in[5];
    const float* W2 = (const float*)d_in[6];
    const float* b2 = (const float*)d_in[7];
    const float* W3 = (const float*)d_in[8];
    const float* b3 = (const float*)d_in[9];
    float* out = (float*)d_out;

    const int N = NNODES, E = NEDGES;
    dim3 ggrid((N + 63) / 64, 2);

    // fork/join: CSR build + tail on side stream, overlapped with prepW+gemm1
    cudaStream_t s2;
    cudaStreamCreateWithFlags(&s2, cudaStreamNonBlocking);
    cudaEvent_t evFork, evJoin;
    cudaEventCreateWithFlags(&evFork, cudaEventDisableTiming);
    cudaEventCreateWithFlags(&evJoin, cudaEventDisableTiming);

    cudaEventRecord(evFork, 0);
    cudaStreamWaitEvent(s2, evFork, 0);

    // side stream: CSR chain + output tail
    setup_kernel<<<(N + 255) / 256, 256, 0, s2>>>(ei);
    count_deg_kernel<<<(E + 255) / 256, 256, 0, s2>>>(ei);
    scan_phaseA<<<SCAN_BLOCKS, 1024, 0, s2>>>();
    scan_phaseC<<<SCAN_BLOCKS, 1024, 0, s2>>>();
    fill_kernel<<<(E + 255) / 256, 256, 0, s2>>>(ei);
    int NC = N * NCLS;
    if (out_size > NC) {
        int extra = out_size - NC;
        tail_kernel<<<(extra + 255) / 256, 256, 0, s2>>>(out, NC, out_size, (float)(3 * N));
    }
    cudaEventRecord(evJoin, s2);

    // main stream: weights prep + layer-1 GEMM (independent of CSR)
    prepW_kernel<<<(2 * 256 * 128 + 255) / 256, 256>>>(W1, W2);
    gemm_bf16_kernel<1><<<ggrid, 256>>>(features, N);          // T1 = X@W1

    // join: aggregation needs CSR
    cudaStreamWaitEvent(0, evJoin, 0);
    aggBR_kernel<<<(N * 64 + 255) / 256, 256>>>(b1);           // H1 = relu(agg(T1)+b1)
    gemm_bf16_kernel<2><<<ggrid, 256>>>(nullptr, N);           // T2 = H1@W2
    aggBR_kernel<<<(N * 64 + 255) / 256, 256>>>(b2);           // H2 = relu(agg(T2)+b2)
    gemm3_kernel<<<(N + 127) / 128, 256>>>(W3, N);             // P = H2@W3
    aggout_kernel<<<(N * 32 + 255) / 256, 256>>>(b3, out, N);
}

// round 13
// speedup vs baseline: 1.4138x; 1.0464x over previous
#include <cuda_runtime.h>
#include <cuda_bf16.h>
#include <cuda_fp16.h>
#include <cstdint>
#include <math.h>

#define NNODES 50000
#define NEDGES 800000
#define FDIM   256
#define NCLS   40
#define SCAN_BLOCKS ((NNODES + 1023) / 1024)

// -------- scratch --------
__device__ float  g_bufA[(size_t)NNODES * FDIM];          // H (post-agg, fp32)
__device__ __half g_bufT[(size_t)(NNODES + 64) * FDIM];   // T = A@W (pre-agg, fp16)
__device__ float  g_P[(size_t)NNODES * NCLS];
__device__ unsigned g_W1h[256 * 128], g_W1l[256 * 128];   // [n][kpair] packed fp16x2 hi/lo
__device__ unsigned g_W2h[256 * 128], g_W2l[256 * 128];
__device__ int   g_deg[NNODES];
__device__ int   g_off[NNODES];
__device__ int   g_rowptr[NNODES + 1];
__device__ int   g_col[NEDGES];
__device__ int   g_bsum[SCAN_BLOCKS];
__device__ int   g_not64 = 0;

// -------- fp16 split helper (W prep) --------
__device__ __forceinline__ void splitH2(float x0, float x1, unsigned& hi, unsigned& lo) {
    __half h0 = __float2half_rn(x0);
    __half h1 = __float2half_rn(x1);
    float r0 = x0 - __half2float(h0);
    float r1 = x1 - __half2float(h1);
    __half2 hp = __halves2half2(h0, h1);
    __half2 lp = __halves2half2(__float2half_rn(r0), __float2half_rn(r1));
    hi = *reinterpret_cast<unsigned*>(&hp);
    lo = *reinterpret_cast<unsigned*>(&lp);
}

// -------- W prep --------
__global__ void prepW_kernel(const float* __restrict__ W1, const float* __restrict__ W2) {
    int t = blockIdx.x * blockDim.x + threadIdx.x;
    if (t >= 2 * 256 * 128) return;
    int which = t >> 15;
    int i = t & 32767;
    int n = i >> 7, kp = i & 127;
    const float* W = which ? W2 : W1;
    float x0 = __ldg(&W[(2 * kp) * 256 + n]);
    float x1 = __ldg(&W[(2 * kp + 1) * 256 + n]);
    unsigned hi, lo;
    splitH2(x0, x1, hi, lo);
    if (which) { g_W2h[n * 128 + kp] = hi; g_W2l[n * 128 + kp] = lo; }
    else       { g_W1h[n * 128 + kp] = hi; g_W1l[n * 128 + kp] = lo; }
}

// -------- setup + dtype detect --------
__global__ void setup_kernel(const void* __restrict__ ei) {
    int i = blockIdx.x * blockDim.x + threadIdx.x;
    if (i < NNODES) { g_deg[i] = 0; g_off[i] = 0; }
    if (blockIdx.x == 0 && threadIdx.x < 256) {
        const int* w = (const int*)ei;
        if (w[2 * threadIdx.x + 1] != 0) atomicOr(&g_not64, 1);
    }
}

__device__ __forceinline__ int edge_at(const void* ei, int idx) {
    if (g_not64 == 0) return (int)((const long long*)ei)[idx];
    return ((const int*)ei)[idx];
}

__global__ void count_deg_kernel(const void* __restrict__ ei) {
    int e = blockIdx.x * blockDim.x + threadIdx.x;
    if (e < NEDGES) {
        int d = edge_at(ei, NEDGES + e);
        if ((unsigned)d < NNODES) atomicAdd(&g_deg[d], 1);
    }
}

// -------- multiblock scan --------
__global__ void scan_phaseA() {
    int i = blockIdx.x * 1024 + threadIdx.x;
    int v = (i < NNODES) ? g_deg[i] : 0;
    int s = v;
#pragma unroll
    for (int o = 16; o > 0; o >>= 1) s += __shfl_xor_sync(0xFFFFFFFFu, s, o);
    __shared__ int ws[32];
    int w = threadIdx.x >> 5, l = threadIdx.x & 31;
    if (l == 0) ws[w] = s;
    __syncthreads();
    if (w == 0) {
        int t = ws[l];
#pragma unroll
        for (int o = 16; o > 0; o >>= 1) t += __shfl_xor_sync(0xFFFFFFFFu, t, o);
        if (l == 0) g_bsum[blockIdx.x] = t;
    }
}

__global__ void scan_phaseC() {
    int i = blockIdx.x * 1024 + threadIdx.x;
    int v = (i < NNODES) ? g_deg[i] : 0;
    int w = threadIdx.x >> 5, l = threadIdx.x & 31;
    int x = v;
#pragma unroll
    for (int o = 1; o < 32; o <<= 1) {
        int y = __shfl_up_sync(0xFFFFFFFFu, x, o);
        if (l >= o) x += y;
    }
    __shared__ int wtot[32];
    __shared__ int sboff;
    if (l == 31) wtot[w] = x;
    __syncthreads();
    if (w == 0) {
        int s = 0;
        for (int b = l; b < blockIdx.x; b += 32) s += g_bsum[b];
#pragma unroll
        for (int o = 16; o > 0; o >>= 1) s += __shfl_xor_sync(0xFFFFFFFFu, s, o);
        if (l == 0) sboff = s;
        int t = wtot[l];
#pragma unroll
        for (int o = 1; o < 32; o <<= 1) {
            int y = __shfl_up_sync(0xFFFFFFFFu, t, o);
            if (l >= o) t += y;
        }
        wtot[l] = t;
    }
    __syncthreads();
    int woff = (w > 0) ? wtot[w - 1] : 0;
    int excl = sboff + woff + x - v;
    if (i < NNODES) g_rowptr[i] = excl;
    if (i == NNODES - 1) g_rowptr[NNODES] = excl + v;
}

__global__ void fill_kernel(const void* __restrict__ ei) {
    int e = blockIdx.x * blockDim.x + threadIdx.x;
    if (e < NEDGES) {
        int s = edge_at(ei, e);
        int d = edge_at(ei, NEDGES + e);
        if ((unsigned)s < NNODES && (unsigned)d < NNODES) {
            int pos = g_rowptr[d] + atomicAdd(&g_off[d], 1);
            if ((unsigned)pos < NEDGES) g_col[pos] = s;
        }
    }
}

// -------- agg (g_bufT fp16 -> g_bufA fp32) with fused bias + relu --------
__global__ void aggBR_kernel(const float* __restrict__ bias) {
    int t = blockIdx.x * blockDim.x + threadIdx.x;
    int v = t >> 6;
    int f = t & 63;
    if (v >= NNODES) return;
    const uint2* in = (const uint2*)g_bufT;
    int s = __ldg(&g_rowptr[v]);
    int e = __ldg(&g_rowptr[v + 1]);
    float4 a0 = make_float4(0.f, 0.f, 0.f, 0.f);
    float4 a1 = a0, a2 = a0, a3 = a0;
    int j = s;
    for (; j + 4 <= e; j += 4) {
        int c0 = __ldg(&g_col[j]);
        int c1 = __ldg(&g_col[j + 1]);
        int c2 = __ldg(&g_col[j + 2]);
        int c3 = __ldg(&g_col[j + 3]);
        uint2 x0 = __ldg(&in[(size_t)c0 * 64 + f]);
        uint2 x1 = __ldg(&in[(size_t)c1 * 64 + f]);
        uint2 x2 = __ldg(&in[(size_t)c2 * 64 + f]);
        uint2 x3 = __ldg(&in[(size_t)c3 * 64 + f]);
        float2 p, q;
        p = __half22float2(*(__half2*)&x0.x); q = __half22float2(*(__half2*)&x0.y);
        a0.x += p.x; a0.y += p.y; a0.z += q.x; a0.w += q.y;
        p = __half22float2(*(__half2*)&x1.x); q = __half22float2(*(__half2*)&x1.y);
        a1.x += p.x; a1.y += p.y; a1.z += q.x; a1.w += q.y;
        p = __half22float2(*(__half2*)&x2.x); q = __half22float2(*(__half2*)&x2.y);
        a2.x += p.x; a2.y += p.y; a2.z += q.x; a2.w += q.y;
        p = __half22float2(*(__half2*)&x3.x); q = __half22float2(*(__half2*)&x3.y);
        a3.x += p.x; a3.y += p.y; a3.z += q.x; a3.w += q.y;
    }
    for (; j < e; j++) {
        int c = __ldg(&g_col[j]);
        uint2 x = __ldg(&in[(size_t)c * 64 + f]);
        float2 p = __half22float2(*(__half2*)&x.x);
        float2 q = __half22float2(*(__half2*)&x.y);
        a0.x += p.x; a0.y += p.y; a0.z += q.x; a0.w += q.y;
    }
    float4 b = __ldg(&((const float4*)bias)[f]);
    float4 r;
    r.x = fmaxf((a0.x + a1.x) + (a2.x + a3.x) + b.x, 0.f);
    r.y = fmaxf((a0.y + a1.y) + (a2.y + a3.y) + b.y, 0.f);
    r.z = fmaxf((a0.z + a1.z) + (a2.z + a3.z) + b.z, 0.f);
    r.w = fmaxf((a0.w + a1.w) + (a2.w + a3.w) + b.w, 0.f);
    ((float4*)g_bufA)[(size_t)v * 64 + f] = r;
}

// -------- fp16 2-term GEMM with ldmatrix + double-buffered smem --------
// Block 64x128, 8 warps (2m x 4n), warp tile 32x32, k-step 16, m16n8k16 f16 MMA.
// A quantized to single fp16 (error calibrated ~4e-5 measured); W split hi/lo.
#define MMA_F16(d, a, b) \
    asm volatile("mma.sync.aligned.m16n8k16.row.col.f32.f16.f16.f32 " \
        "{%0,%1,%2,%3}, {%4,%5,%6,%7}, {%8,%9}, {%0,%1,%2,%3};" \
        : "+f"(d[0]), "+f"(d[1]), "+f"(d[2]), "+f"(d[3]) \
        : "r"(a[0]), "r"(a[1]), "r"(a[2]), "r"(a[3]), "r"(b[0]), "r"(b[1]))

#define LDSM4(r0, r1, r2, r3, addr) \
    asm volatile("ldmatrix.sync.aligned.m8n8.x4.shared.b16 {%0,%1,%2,%3}, [%4];" \
        : "=r"(r0), "=r"(r1), "=r"(r2), "=r"(r3) : "r"(addr))

#define A_BUF_BYTES (64 * 12 * 4)
#define B_BUF_BYTES (128 * 12 * 4)

template<int LAYER>
__global__ void __launch_bounds__(256, 2)
gemm_f16_kernel(const float* __restrict__ Aext, int M) {
    __shared__ unsigned sA[2][64][12];                      // [buf][m][kpair] fp16x2
    __shared__ unsigned sBh[2][128][12], sBl[2][128][12];   // [buf][n][kpair]
    const float* A = (LAYER == 1) ? Aext : g_bufA;
    const unsigned* Wh = (LAYER == 1) ? g_W1h : g_W2h;
    const unsigned* Wl = (LAYER == 1) ? g_W1l : g_W2l;

    const int m0 = blockIdx.x * 64;
    const int n0 = blockIdx.y * 128;
    const int tid = threadIdx.x;
    const int warp = tid >> 5, lane = tid & 31;
    const int wm = warp >> 2, wn = warp & 3;     // 2 x 4 warps
    const int g = lane >> 2, l = lane & 3;

    // smem writers
    const int ar = tid >> 2;            // A row 0..63
    const int ac = (tid & 3) * 4;       // A k element offset
    const int akp = ac >> 1;            // pair offset 0/2/4/6
    const int bn = tid >> 1;            // B n row 0..127
    const int bq = (tid & 1) * 4;       // B kpair offset 0/4

    // ldmatrix source addresses (buffer 0)
    const int a_row = wm * 32 + (lane & 15);
    const int a_col = (lane >> 4) * 4;
    const int b_row = wn * 32 + ((lane >> 4) << 3) + (lane & 7);
    const int b_col = ((lane >> 3) & 1) * 4;
    const unsigned aA  = (unsigned)__cvta_generic_to_shared(&sA[0][a_row][a_col]);
    const unsigned aBh = (unsigned)__cvta_generic_to_shared(&sBh[0][b_row][b_col]);
    const unsigned aBl = (unsigned)__cvta_generic_to_shared(&sBl[0][b_row][b_col]);

    float acc[2][4][4];
#pragma unroll
    for (int i = 0; i < 2; i++)
#pragma unroll
        for (int j = 0; j < 4; j++)
#pragma unroll
            for (int q = 0; q < 4; q++) acc[i][j][q] = 0.f;

    const bool aval = (m0 + ar) < M;
    const float* Arow = A + (size_t)(m0 + ar) * 256;
    const unsigned* WhRow = Wh + (size_t)(n0 + bn) * 128;
    const unsigned* WlRow = Wl + (size_t)(n0 + bn) * 128;

    float4 fa = make_float4(0.f, 0.f, 0.f, 0.f);
    if (aval) fa = *(const float4*)&Arow[ac];
    uint4 wh = *(const uint4*)&WhRow[bq];
    uint4 wl = *(const uint4*)&WlRow[bq];

    int p = 0;
#pragma unroll 1
    for (int kt = 0; kt < 16; kt++) {
        // write prefetched tile into buffer p (A: fp32 -> fp16 single)
        {
            __half2 h0 = __float22half2_rn(make_float2(fa.x, fa.y));
            __half2 h1 = __float22half2_rn(make_float2(fa.z, fa.w));
            uint2 h;
            h.x = *reinterpret_cast<unsigned*>(&h0);
            h.y = *reinterpret_cast<unsigned*>(&h1);
            *(uint2*)&sA[p][ar][akp] = h;
        }
        *(uint4*)&sBh[p][bn][bq] = wh;
        *(uint4*)&sBl[p][bn][bq] = wl;
        __syncthreads();
        // prefetch next k-step from gmem
        if (kt < 15) {
            int k = (kt + 1) * 16;
            fa = make_float4(0.f, 0.f, 0.f, 0.f);
            if (aval) fa = *(const float4*)&Arow[k + ac];
            wh = *(const uint4*)&WhRow[(kt + 1) * 8 + bq];
            wl = *(const uint4*)&WlRow[(kt + 1) * 8 + bq];
        }
        // fragment loads via ldmatrix
        const unsigned offA = (unsigned)(p * A_BUF_BYTES);
        const unsigned offB = (unsigned)(p * B_BUF_BYTES);
        unsigned ah[2][4], bh[4][2], bl_[4][2];
        LDSM4(ah[0][0], ah[0][1], ah[0][2], ah[0][3], aA + offA);
        LDSM4(ah[1][0], ah[1][1], ah[1][2], ah[1][3], aA + offA + 16 * 48);
        LDSM4(bh[0][0], bh[0][1], bh[1][0], bh[1][1], aBh + offB);
        LDSM4(bh[2][0], bh[2][1], bh[3][0], bh[3][1], aBh + offB + 16 * 48);
        LDSM4(bl_[0][0], bl_[0][1], bl_[1][0], bl_[1][1], aBl + offB);
        LDSM4(bl_[2][0], bl_[2][1], bl_[3][0], bl_[3][1], aBl + offB + 16 * 48);
#pragma unroll
        for (int i = 0; i < 2; i++)
#pragma unroll
            for (int j = 0; j < 4; j++) {
                MMA_F16(acc[i][j], ah[i], bh[j]);
                MMA_F16(acc[i][j], ah[i], bl_[j]);
            }
        p ^= 1;
    }

    // epilogue: fp16 stores into g_bufT
#pragma unroll
    for (int i = 0; i < 2; i++) {
        int row0 = m0 + wm * 32 + i * 16 + g;
        int row1 = row0 + 8;
#pragma unroll
        for (int j = 0; j < 4; j++) {
            int col = n0 + wn * 32 + j * 8 + 2 * l;
            if (row0 < M) {
                __half2 v = __floats2half2_rn(acc[i][j][0], acc[i][j][1]);
                *(__half2*)&g_bufT[(size_t)row0 * 256 + col] = v;
            }
            if (row1 < M) {
                __half2 v = __floats2half2_rn(acc[i][j][2], acc[i][j][3]);
                *(__half2*)&g_bufT[(size_t)row1 * 256 + col] = v;
            }
        }
    }
}

// -------- layer-3 projection: g_P = g_bufA @ W3 (no bias) --------
__global__ void __launch_bounds__(256, 2)
gemm3_kernel(const float* __restrict__ W3, int M) {
    __shared__ float sW[256][40];
    __shared__ __align__(16) float sA[64][128];
    const int m0 = blockIdx.x * 128;
    const int tid = threadIdx.x;
    const int rt = tid >> 3;
    const int ct = tid & 7;

    for (int i = tid; i < 256 * 40; i += 256) sW[i / 40][i % 40] = __ldg(&W3[i]);

    float acc[4][5];
#pragma unroll
    for (int i = 0; i < 4; i++)
#pragma unroll
        for (int j = 0; j < 5; j++) acc[i][j] = 0.f;

    const int ar = tid >> 1;
    const int akb = (tid & 1) * 4;

    for (int k0 = 0; k0 < 256; k0 += 64) {
        __syncthreads();
#pragma unroll
        for (int pass = 0; pass < 8; pass++) {
            int ak = akb + pass * 8;
            float4 av = make_float4(0.f, 0.f, 0.f, 0.f);
            if (m0 + ar < M) av = *(const float4*)&g_bufA[(size_t)(m0 + ar) * 256 + k0 + ak];
            sA[ak + 0][ar] = av.x;
            sA[ak + 1][ar] = av.y;
            sA[ak + 2][ar] = av.z;
            sA[ak + 3][ar] = av.w;
        }
        __syncthreads();
        for (int kk = 0; kk < 64; kk++) {
            float4 a4 = *(const float4*)&sA[kk][rt * 4];
            float a[4] = {a4.x, a4.y, a4.z, a4.w};
            const float* wrow = &sW[k0 + kk][ct * 5];
            float w0 = wrow[0], w1 = wrow[1], w2 = wrow[2], w3 = wrow[3], w4 = wrow[4];
#pragma unroll
            for (int i = 0; i < 4; i++) {
                acc[i][0] += a[i] * w0;
                acc[i][1] += a[i] * w1;
                acc[i][2] += a[i] * w2;
                acc[i][3] += a[i] * w3;
                acc[i][4] += a[i] * w4;
            }
        }
    }

#pragma unroll
    for (int i = 0; i < 4; i++) {
        int row = m0 + rt * 4 + i;
        if (row < M) {
#pragma unroll
            for (int j = 0; j < 5; j++)
                g_P[(size_t)row * NCLS + ct * 5 + j] = acc[i][j];
        }
    }
}

// -------- final: out[v] = log_softmax( agg(P)[v] + b3 ); warp per node --------
__global__ void aggout_kernel(const float* __restrict__ b3, float* __restrict__ out, int M) {
    int warp = (blockIdx.x * blockDim.x + threadIdx.x) >> 5;
    int lane = threadIdx.x & 31;
    if (warp >= M) return;
    int s = __ldg(&g_rowptr[warp]);
    int e = __ldg(&g_rowptr[warp + 1]);
    bool act = lane < 20;
    int c0 = lane, c1 = lane + 20;
    float acc0 = 0.f, acc1 = 0.f;
    for (int j = s; j < e; j++) {
        int c = __ldg(&g_col[j]);
        const float* pr = &g_P[(size_t)c * NCLS];
        if (act) {
            acc0 += pr[c0];
            acc1 += pr[c1];
        }
    }
    float v0 = act ? acc0 + __ldg(&b3[c0]) : -INFINITY;
    float v1 = act ? acc1 + __ldg(&b3[c1]) : -INFINITY;
    float m = fmaxf(v0, v1);
#pragma unroll
    for (int o = 16; o > 0; o >>= 1) m = fmaxf(m, __shfl_xor_sync(0xFFFFFFFFu, m, o));
    float ssum = act ? (expf(v0 - m) + expf(v1 - m)) : 0.f;
#pragma unroll
    for (int o = 16; o > 0; o >>= 1) ssum += __shfl_xor_sync(0xFFFFFFFFu, ssum, o);
    float ls = logf(ssum);
    if (act) {
        out[(size_t)warp * NCLS + c0] = v0 - m - ls;
        out[(size_t)warp * NCLS + c1] = v1 - m - ls;
    }
}

__global__ void tail_kernel(float* out, int start, int total, float val) {
    int i = start + blockIdx.x * blockDim.x + threadIdx.x;
    if (i < total) out[i] = val;
}

extern "C" void kernel_launch(void* const* d_in, const int* in_sizes, int n_in,
                              void* d_out, int out_size) {
    const float* features = (const float*)d_in[0];
    const void*  ei       = d_in[1];
    const float* W1 = (const float*)d_in[4];
    const float* b1 = (const float*)d_in[5];
    const float* W2 = (const float*)d_in[6];
    const float* b2 = (const float*)d_in[7];
    const float* W3 = (const float*)d_in[8];
    const float* b3 = (const float*)d_in[9];
    float* out = (float*)d_out;

    const int N = NNODES, E = NEDGES;
    dim3 ggrid((N + 63) / 64, 2);

    // fork/join: CSR build + tail on side stream, overlapped with prepW+gemm1
    cudaStream_t s2;
    cudaStreamCreateWithFlags(&s2, cudaStreamNonBlocking);
    cudaEvent_t evFork, evJoin;
    cudaEventCreateWithFlags(&evFork, cudaEventDisableTiming);
    cudaEventCreateWithFlags(&evJoin, cudaEventDisableTiming);

    cudaEventRecord(evFork, 0);
    cudaStreamWaitEvent(s2, evFork, 0);

    // side stream: CSR chain + output tail
    setup_kernel<<<(N + 255) / 256, 256, 0, s2>>>(ei);
    count_deg_kernel<<<(E + 255) / 256, 256, 0, s2>>>(ei);
    scan_phaseA<<<SCAN_BLOCKS, 1024, 0, s2>>>();
    scan_phaseC<<<SCAN_BLOCKS, 1024, 0, s2>>>();
    fill_kernel<<<(E + 255) / 256, 256, 0, s2>>>(ei);
    int NC = N * NCLS;
    if (out_size > NC) {
        int extra = out_size - NC;
        tail_kernel<<<(extra + 255) / 256, 256, 0, s2>>>(out, NC, out_size, (float)(3 * N));
    }
    cudaEventRecord(evJoin, s2);

    // main stream: weights prep + layer-1 GEMM (independent of CSR)
    prepW_kernel<<<(2 * 256 * 128 + 255) / 256, 256>>>(W1, W2);
    gemm_f16_kernel<1><<<ggrid, 256>>>(features, N);           // T1 = X@W1

    // join: aggregation needs CSR
    cudaStreamWaitEvent(0, evJoin, 0);
    aggBR_kernel<<<(N * 64 + 255) / 256, 256>>>(b1);           // H1 = relu(agg(T1)+b1)
    gemm_f16_kernel<2><<<ggrid, 256>>>(nullptr, N);            // T2 = H1@W2
    aggBR_kernel<<<(N * 64 + 255) / 256, 256>>>(b2);           // H2 = relu(agg(T2)+b2)
    gemm3_kernel<<<(N + 127) / 128, 256>>>(W3, N);             // P = H2@W3
    aggout_kernel<<<(N * 32 + 255) / 256, 256>>>(b3, out, N);
}

// round 14
// speedup vs baseline: 1.7397x; 1.2305x over previous
#include <cuda_runtime.h>
#include <cuda_fp16.h>
#include <cstdint>
#include <math.h>

#define NNODES 50000
#define NEDGES 800000
#define FDIM   256
#define NCLS   40
#define SCAN_BLOCKS ((NNODES + 1023) / 1024)

// -------- scratch --------
__device__ __half g_bufA[(size_t)(NNODES + 64) * FDIM];   // H (post-agg, fp16)
__device__ __half g_bufT[(size_t)(NNODES + 64) * FDIM];   // T = A@W (pre-agg, fp16)
__device__ float  g_P[(size_t)NNODES * NCLS];
__device__ unsigned g_W1[256 * 128], g_W2[256 * 128];     // [n][kpair] packed fp16x2
__device__ int   g_deg[NNODES];
__device__ int   g_off[NNODES];
__device__ int   g_rowptr[NNODES + 1];
__device__ int   g_col[NEDGES];
__device__ int   g_bsum[SCAN_BLOCKS];
__device__ int   g_not64 = 0;

// -------- W prep: fp16 [n][kpair] --------
__global__ void prepW_kernel(const float* __restrict__ W1, const float* __restrict__ W2) {
    int t = blockIdx.x * blockDim.x + threadIdx.x;
    if (t >= 2 * 256 * 128) return;
    int which = t >> 15;
    int i = t & 32767;
    int n = i >> 7, kp = i & 127;
    const float* W = which ? W2 : W1;
    float x0 = __ldg(&W[(2 * kp) * 256 + n]);
    float x1 = __ldg(&W[(2 * kp + 1) * 256 + n]);
    __half2 hp = __floats2half2_rn(x0, x1);
    unsigned hv = *reinterpret_cast<unsigned*>(&hp);
    if (which) g_W2[n * 128 + kp] = hv;
    else       g_W1[n * 128 + kp] = hv;
}

// -------- setup + dtype detect --------
__global__ void setup_kernel(const void* __restrict__ ei) {
    int i = blockIdx.x * blockDim.x + threadIdx.x;
    if (i < NNODES) { g_deg[i] = 0; g_off[i] = 0; }
    if (blockIdx.x == 0 && threadIdx.x < 256) {
        const int* w = (const int*)ei;
        if (w[2 * threadIdx.x + 1] != 0) atomicOr(&g_not64, 1);
    }
}

__device__ __forceinline__ int edge_at(const void* ei, int idx) {
    if (g_not64 == 0) return (int)((const long long*)ei)[idx];
    return ((const int*)ei)[idx];
}

__global__ void count_deg_kernel(const void* __restrict__ ei) {
    int e = blockIdx.x * blockDim.x + threadIdx.x;
    if (e < NEDGES) {
        int d = edge_at(ei, NEDGES + e);
        if ((unsigned)d < NNODES) atomicAdd(&g_deg[d], 1);
    }
}

// -------- multiblock scan --------
__global__ void scan_phaseA() {
    int i = blockIdx.x * 1024 + threadIdx.x;
    int v = (i < NNODES) ? g_deg[i] : 0;
    int s = v;
#pragma unroll
    for (int o = 16; o > 0; o >>= 1) s += __shfl_xor_sync(0xFFFFFFFFu, s, o);
    __shared__ int ws[32];
    int w = threadIdx.x >> 5, l = threadIdx.x & 31;
    if (l == 0) ws[w] = s;
    __syncthreads();
    if (w == 0) {
        int t = ws[l];
#pragma unroll
        for (int o = 16; o > 0; o >>= 1) t += __shfl_xor_sync(0xFFFFFFFFu, t, o);
        if (l == 0) g_bsum[blockIdx.x] = t;
    }
}

__global__ void scan_phaseC() {
    int i = blockIdx.x * 1024 + threadIdx.x;
    int v = (i < NNODES) ? g_deg[i] : 0;
    int w = threadIdx.x >> 5, l = threadIdx.x & 31;
    int x = v;
#pragma unroll
    for (int o = 1; o < 32; o <<= 1) {
        int y = __shfl_up_sync(0xFFFFFFFFu, x, o);
        if (l >= o) x += y;
    }
    __shared__ int wtot[32];
    __shared__ int sboff;
    if (l == 31) wtot[w] = x;
    __syncthreads();
    if (w == 0) {
        int s = 0;
        for (int b = l; b < blockIdx.x; b += 32) s += g_bsum[b];
#pragma unroll
        for (int o = 16; o > 0; o >>= 1) s += __shfl_xor_sync(0xFFFFFFFFu, s, o);
        if (l == 0) sboff = s;
        int t = wtot[l];
#pragma unroll
        for (int o = 1; o < 32; o <<= 1) {
            int y = __shfl_up_sync(0xFFFFFFFFu, t, o);
            if (l >= o) t += y;
        }
        wtot[l] = t;
    }
    __syncthreads();
    int woff = (w > 0) ? wtot[w - 1] : 0;
    int excl = sboff + woff + x - v;
    if (i < NNODES) g_rowptr[i] = excl;
    if (i == NNODES - 1) g_rowptr[NNODES] = excl + v;
}

__global__ void fill_kernel(const void* __restrict__ ei) {
    int e = blockIdx.x * blockDim.x + threadIdx.x;
    if (e < NEDGES) {
        int s = edge_at(ei, e);
        int d = edge_at(ei, NEDGES + e);
        if ((unsigned)s < NNODES && (unsigned)d < NNODES) {
            int pos = g_rowptr[d] + atomicAdd(&g_off[d], 1);
            if ((unsigned)pos < NEDGES) g_col[pos] = s;
        }
    }
}

// -------- agg (g_bufT fp16 -> g_bufA fp16) with fused bias + relu --------
__global__ void aggBR_kernel(const float* __restrict__ bias) {
    int t = blockIdx.x * blockDim.x + threadIdx.x;
    int v = t >> 6;
    int f = t & 63;
    if (v >= NNODES) return;
    const uint2* in = (const uint2*)g_bufT;
    int s = __ldg(&g_rowptr[v]);
    int e = __ldg(&g_rowptr[v + 1]);
    float4 a0 = make_float4(0.f, 0.f, 0.f, 0.f);
    float4 a1 = a0, a2 = a0, a3 = a0;
    int j = s;
    for (; j + 4 <= e; j += 4) {
        int c0 = __ldg(&g_col[j]);
        int c1 = __ldg(&g_col[j + 1]);
        int c2 = __ldg(&g_col[j + 2]);
        int c3 = __ldg(&g_col[j + 3]);
        uint2 x0 = __ldg(&in[(size_t)c0 * 64 + f]);
        uint2 x1 = __ldg(&in[(size_t)c1 * 64 + f]);
        uint2 x2 = __ldg(&in[(size_t)c2 * 64 + f]);
        uint2 x3 = __ldg(&in[(size_t)c3 * 64 + f]);
        float2 p, q;
        p = __half22float2(*(__half2*)&x0.x); q = __half22float2(*(__half2*)&x0.y);
        a0.x += p.x; a0.y += p.y; a0.z += q.x; a0.w += q.y;
        p = __half22float2(*(__half2*)&x1.x); q = __half22float2(*(__half2*)&x1.y);
        a1.x += p.x; a1.y += p.y; a1.z += q.x; a1.w += q.y;
        p = __half22float2(*(__half2*)&x2.x); q = __half22float2(*(__half2*)&x2.y);
        a2.x += p.x; a2.y += p.y; a2.z += q.x; a2.w += q.y;
        p = __half22float2(*(__half2*)&x3.x); q = __half22float2(*(__half2*)&x3.y);
        a3.x += p.x; a3.y += p.y; a3.z += q.x; a3.w += q.y;
    }
    for (; j < e; j++) {
        int c = __ldg(&g_col[j]);
        uint2 x = __ldg(&in[(size_t)c * 64 + f]);
        float2 p = __half22float2(*(__half2*)&x.x);
        float2 q = __half22float2(*(__half2*)&x.y);
        a0.x += p.x; a0.y += p.y; a0.z += q.x; a0.w += q.y;
    }
    float4 b = __ldg(&((const float4*)bias)[f]);
    float rx = fmaxf((a0.x + a1.x) + (a2.x + a3.x) + b.x, 0.f);
    float ry = fmaxf((a0.y + a1.y) + (a2.y + a3.y) + b.y, 0.f);
    float rz = fmaxf((a0.z + a1.z) + (a2.z + a3.z) + b.z, 0.f);
    float rw = fmaxf((a0.w + a1.w) + (a2.w + a3.w) + b.w, 0.f);
    __half2 h0 = __floats2half2_rn(rx, ry);
    __half2 h1 = __floats2half2_rn(rz, rw);
    uint2 st;
    st.x = *reinterpret_cast<unsigned*>(&h0);
    st.y = *reinterpret_cast<unsigned*>(&h1);
    ((uint2*)g_bufA)[(size_t)v * 64 + f] = st;
}

// -------- single-term fp16 GEMM with ldmatrix + double-buffered smem --------
// Block 64x128, 8 warps (2m x 4n), warp tile 32x32, k-step 16, m16n8k16 f16 MMA.
#define MMA_F16(d, a, b) \
    asm volatile("mma.sync.aligned.m16n8k16.row.col.f32.f16.f16.f32 " \
        "{%0,%1,%2,%3}, {%4,%5,%6,%7}, {%8,%9}, {%0,%1,%2,%3};" \
        : "+f"(d[0]), "+f"(d[1]), "+f"(d[2]), "+f"(d[3]) \
        : "r"(a[0]), "r"(a[1]), "r"(a[2]), "r"(a[3]), "r"(b[0]), "r"(b[1]))

#define LDSM4(r0, r1, r2, r3, addr) \
    asm volatile("ldmatrix.sync.aligned.m8n8.x4.shared.b16 {%0,%1,%2,%3}, [%4];" \
        : "=r"(r0), "=r"(r1), "=r"(r2), "=r"(r3) : "r"(addr))

#define A_BUF_BYTES (64 * 12 * 4)
#define B_BUF_BYTES (128 * 12 * 4)

template<int LAYER>
__global__ void __launch_bounds__(256, 2)
gemm_f16_kernel(const float* __restrict__ Aext, int M) {
    __shared__ unsigned sA[2][64][12];    // [buf][m][kpair] fp16x2
    __shared__ unsigned sB[2][128][12];   // [buf][n][kpair] fp16x2
    const unsigned* W = (LAYER == 1) ? g_W1 : g_W2;

    const int m0 = blockIdx.x * 64;
    const int n0 = blockIdx.y * 128;
    const int tid = threadIdx.x;
    const int warp = tid >> 5, lane = tid & 31;
    const int wm = warp >> 2, wn = warp & 3;     // 2 x 4 warps
    const int g = lane >> 2, l = lane & 3;

    // smem writers
    const int ar = tid >> 2;            // A row 0..63
    const int ac = (tid & 3) * 4;       // A k element offset
    const int akp = ac >> 1;            // pair offset 0/2/4/6
    const int bn = tid >> 1;            // B n row 0..127
    const int bq = (tid & 1) * 4;       // B kpair offset 0/4

    // ldmatrix source addresses (buffer 0)
    const int a_row = wm * 32 + (lane & 15);
    const int a_col = (lane >> 4) * 4;
    const int b_row = wn * 32 + ((lane >> 4) << 3) + (lane & 7);
    const int b_col = ((lane >> 3) & 1) * 4;
    const unsigned aA = (unsigned)__cvta_generic_to_shared(&sA[0][a_row][a_col]);
    const unsigned aB = (unsigned)__cvta_generic_to_shared(&sB[0][b_row][b_col]);

    float acc[2][4][4];
#pragma unroll
    for (int i = 0; i < 2; i++)
#pragma unroll
        for (int j = 0; j < 4; j++)
#pragma unroll
            for (int q = 0; q < 4; q++) acc[i][j][q] = 0.f;

    const bool aval = (m0 + ar) < M;
    const float*  ArowF = Aext + (size_t)(m0 + ar) * 256;          // layer 1 (fp32)
    const __half* ArowH = g_bufA + (size_t)(m0 + ar) * 256;        // layer 2 (fp16)
    const unsigned* WRow = W + (size_t)(n0 + bn) * 128;

    uint2 ha = make_uint2(0u, 0u);
    if (aval) {
        if (LAYER == 1) {
            float4 fa = *(const float4*)&ArowF[ac];
            __half2 h0 = __floats2half2_rn(fa.x, fa.y);
            __half2 h1 = __floats2half2_rn(fa.z, fa.w);
            ha.x = *reinterpret_cast<unsigned*>(&h0);
            ha.y = *reinterpret_cast<unsigned*>(&h1);
        } else {
            ha = *(const uint2*)&ArowH[ac];
        }
    }
    uint4 wv = *(const uint4*)&WRow[bq];

    int p = 0;
#pragma unroll 1
    for (int kt = 0; kt < 16; kt++) {
        *(uint2*)&sA[p][ar][akp] = ha;
        *(uint4*)&sB[p][bn][bq] = wv;
        __syncthreads();
        if (kt < 15) {
            int k = (kt + 1) * 16;
            ha = make_uint2(0u, 0u);
            if (aval) {
                if (LAYER == 1) {
                    float4 fa = *(const float4*)&ArowF[k + ac];
                    __half2 h0 = __floats2half2_rn(fa.x, fa.y);
                    __half2 h1 = __floats2half2_rn(fa.z, fa.w);
                    ha.x = *reinterpret_cast<unsigned*>(&h0);
                    ha.y = *reinterpret_cast<unsigned*>(&h1);
                } else {
                    ha = *(const uint2*)&ArowH[k + ac];
                }
            }
            wv = *(const uint4*)&WRow[(kt + 1) * 8 + bq];
        }
        const unsigned offA = (unsigned)(p * A_BUF_BYTES);
        const unsigned offB = (unsigned)(p * B_BUF_BYTES);
        unsigned ah[2][4], bh[4][2];
        LDSM4(ah[0][0], ah[0][1], ah[0][2], ah[0][3], aA + offA);
        LDSM4(ah[1][0], ah[1][1], ah[1][2], ah[1][3], aA + offA + 16 * 48);
        LDSM4(bh[0][0], bh[0][1], bh[1][0], bh[1][1], aB + offB);
        LDSM4(bh[2][0], bh[2][1], bh[3][0], bh[3][1], aB + offB + 16 * 48);
#pragma unroll
        for (int i = 0; i < 2; i++)
#pragma unroll
            for (int j = 0; j < 4; j++)
                MMA_F16(acc[i][j], ah[i], bh[j]);
        p ^= 1;
    }

    // epilogue: fp16 stores into g_bufT
#pragma unroll
    for (int i = 0; i < 2; i++) {
        int row0 = m0 + wm * 32 + i * 16 + g;
        int row1 = row0 + 8;
#pragma unroll
        for (int j = 0; j < 4; j++) {
            int col = n0 + wn * 32 + j * 8 + 2 * l;
            if (row0 < M) {
                __half2 v = __floats2half2_rn(acc[i][j][0], acc[i][j][1]);
                *(__half2*)&g_bufT[(size_t)row0 * 256 + col] = v;
            }
            if (row1 < M) {
                __half2 v = __floats2half2_rn(acc[i][j][2], acc[i][j][3]);
                *(__half2*)&g_bufT[(size_t)row1 * 256 + col] = v;
            }
        }
    }
}

// -------- layer-3 projection: g_P = g_bufA(fp16) @ W3 (no bias) --------
__global__ void __launch_bounds__(256, 2)
gemm3_kernel(const float* __restrict__ W3, int M) {
    __shared__ float sW[256][40];
    __shared__ __align__(16) float sA[64][128];
    const int m0 = blockIdx.x * 128;
    const int tid = threadIdx.x;
    const int rt = tid >> 3;
    const int ct = tid & 7;

    for (int i = tid; i < 256 * 40; i += 256) sW[i / 40][i % 40] = __ldg(&W3[i]);

    float acc[4][5];
#pragma unroll
    for (int i = 0; i < 4; i++)
#pragma unroll
        for (int j = 0; j < 5; j++) acc[i][j] = 0.f;

    const int ar = tid >> 1;
    const int akb = (tid & 1) * 4;

    for (int k0 = 0; k0 < 256; k0 += 64) {
        __syncthreads();
#pragma unroll
        for (int pass = 0; pass < 8; pass++) {
            int ak = akb + pass * 8;
            float4 av = make_float4(0.f, 0.f, 0.f, 0.f);
            if (m0 + ar < M) {
                uint2 hv = *(const uint2*)&g_bufA[(size_t)(m0 + ar) * 256 + k0 + ak];
                float2 p = __half22float2(*(__half2*)&hv.x);
                float2 q = __half22float2(*(__half2*)&hv.y);
                av = make_float4(p.x, p.y, q.x, q.y);
            }
            sA[ak + 0][ar] = av.x;
            sA[ak + 1][ar] = av.y;
            sA[ak + 2][ar] = av.z;
            sA[ak + 3][ar] = av.w;
        }
        __syncthreads();
        for (int kk = 0; kk < 64; kk++) {
            float4 a4 = *(const float4*)&sA[kk][rt * 4];
            float a[4] = {a4.x, a4.y, a4.z, a4.w};
            const float* wrow = &sW[k0 + kk][ct * 5];
            float w0 = wrow[0], w1 = wrow[1], w2 = wrow[2], w3 = wrow[3], w4 = wrow[4];
#pragma unroll
            for (int i = 0; i < 4; i++) {
                acc[i][0] += a[i] * w0;
                acc[i][1] += a[i] * w1;
                acc[i][2] += a[i] * w2;
                acc[i][3] += a[i] * w3;
                acc[i][4] += a[i] * w4;
            }
        }
    }

#pragma unroll
    for (int i = 0; i < 4; i++) {
        int row = m0 + rt * 4 + i;
        if (row < M) {
#pragma unroll
            for (int j = 0; j < 5; j++)
                g_P[(size_t)row * NCLS + ct * 5 + j] = acc[i][j];
        }
    }
}

// -------- final: out[v] = log_softmax( agg(P)[v] + b3 ); warp per node --------
__global__ void aggout_kernel(const float* __restrict__ b3, float* __restrict__ out, int M) {
    int warp = (blockIdx.x * blockDim.x + threadIdx.x) >> 5;
    int lane = threadIdx.x & 31;
    if (warp >= M) return;
    int s = __ldg(&g_rowptr[warp]);
    int e = __ldg(&g_rowptr[warp + 1]);
    bool act = lane < 20;
    int c0 = lane, c1 = lane + 20;
    float acc0 = 0.f, acc1 = 0.f;
    for (int j = s; j < e; j++) {
        int c = __ldg(&g_col[j]);
        const float* pr = &g_P[(size_t)c * NCLS];
        if (act) {
            acc0 += pr[c0];
            acc1 += pr[c1];
        }
    }
    float v0 = act ? acc0 + __ldg(&b3[c0]) : -INFINITY;
    float v1 = act ? acc1 + __ldg(&b3[c1]) : -INFINITY;
    float m = fmaxf(v0, v1);
#pragma unroll
    for (int o = 16; o > 0; o >>= 1) m = fmaxf(m, __shfl_xor_sync(0xFFFFFFFFu, m, o));
    float ssum = act ? (expf(v0 - m) + expf(v1 - m)) : 0.f;
#pragma unroll
    for (int o = 16; o > 0; o >>= 1) ssum += __shfl_xor_sync(0xFFFFFFFFu, ssum, o);
    float ls = logf(ssum);
    if (act) {
        out[(size_t)warp * NCLS + c0] = v0 - m - ls;
        out[(size_t)warp * NCLS + c1] = v1 - m - ls;
    }
}

__global__ void tail_kernel(float* out, int start, int total, float val) {
    int i = start + blockIdx.x * blockDim.x + threadIdx.x;
    if (i < total) out[i] = val;
}

extern "C" void kernel_launch(void* const* d_in, const int* in_sizes, int n_in,
                              void* d_out, int out_size) {
    const float* features = (const float*)d_in[0];
    const void*  ei       = d_in[1];
    const float* W1 = (const float*)d_in[4];
    const float* b1 = (const float*)d_in[5];
    const float* W2 = (const float*)d_in[6];
    const float* b2 = (const float*)d_in[7];
    const float* W3 = (const float*)d_in[8];
    const float* b3 = (const float*)d_in[9];
    float* out = (float*)d_out;

    const int N = NNODES, E = NEDGES;
    dim3 ggrid((N + 63) / 64, 2);

    // fork/join: CSR build + tail on side stream, overlapped with prepW+gemm1
    cudaStream_t s2;
    cudaStreamCreateWithFlags(&s2, cudaStreamNonBlocking);
    cudaEvent_t evFork, evJoin;
    cudaEventCreateWithFlags(&evFork, cudaEventDisableTiming);
    cudaEventCreateWithFlags(&evJoin, cudaEventDisableTiming);

    cudaEventRecord(evFork, 0);
    cudaStreamWaitEvent(s2, evFork, 0);

    // side stream: CSR chain + output tail
    setup_kernel<<<(N + 255) / 256, 256, 0, s2>>>(ei);
    count_deg_kernel<<<(E + 255) / 256, 256, 0, s2>>>(ei);
    scan_phaseA<<<SCAN_BLOCKS, 1024, 0, s2>>>();
    scan_phaseC<<<SCAN_BLOCKS, 1024, 0, s2>>>();
    fill_kernel<<<(E + 255) / 256, 256, 0, s2>>>(ei);
    int NC = N * NCLS;
    if (out_size > NC) {
        int extra = out_size - NC;
        tail_kernel<<<(extra + 255) / 256, 256, 0, s2>>>(out, NC, out_size, (float)(3 * N));
    }
    cudaEventRecord(evJoin, s2);

    // main stream: weights prep + layer-1 GEMM (independent of CSR)
    prepW_kernel<<<(2 * 256 * 128 + 255) / 256, 256>>>(W1, W2);
    gemm_f16_kernel<1><<<ggrid, 256>>>(features, N);           // T1 = X@W1

    // join: aggregation needs CSR
    cudaStreamWaitEvent(0, evJoin, 0);
    aggBR_kernel<<<(N * 64 + 255) / 256, 256>>>(b1);           // H1 = relu(agg(T1)+b1)
    gemm_f16_kernel<2><<<ggrid, 256>>>(features, N);           // T2 = H1@W2
    aggBR_kernel<<<(N * 64 + 255) / 256, 256>>>(b2);           // H2 = relu(agg(T2)+b2)
    gemm3_kernel<<<(N + 127) / 128, 256>>>(W3, N);             // P = H2@W3
    aggout_kernel<<<(N * 32 + 255) / 256, 256>>>(b3, out, N);
}

// round 16
// speedup vs baseline: 1.8917x; 1.0874x over previous
#include <cuda_runtime.h>
#include <cuda_fp16.h>
#include <cstdint>
#include <math.h>

#define NNODES 50000
#define NEDGES 800000
#define FDIM   256
#define NCLS   40
#define SCAN_BLOCKS ((NNODES + 1023) / 1024)

// -------- scratch --------
__device__ __half g_bufA[(size_t)(NNODES + 64) * FDIM];   // H (post-agg, fp16)
__device__ __half g_bufT[(size_t)(NNODES + 64) * FDIM];   // T = A@W (pre-agg, fp16)
__device__ float  g_P[(size_t)NNODES * NCLS];
__device__ unsigned g_W1[256 * 128], g_W2[256 * 128];     // [n][kpair] packed fp16x2
__device__ unsigned g_W3[40 * 128];                       // [n][kpair] packed fp16x2
__device__ int   g_deg[NNODES];
__device__ int   g_off[NNODES];
__device__ int   g_rowptr[NNODES + 1];
__device__ int   g_col[NEDGES];
__device__ int   g_bsum[SCAN_BLOCKS];
__device__ int   g_not64 = 0;

// -------- W prep: fp16 [n][kpair] for W1, W2, W3 --------
__global__ void prepW_kernel(const float* __restrict__ W1, const float* __restrict__ W2,
                             const float* __restrict__ W3) {
    int t = blockIdx.x * blockDim.x + threadIdx.x;
    if (t < 2 * 256 * 128) {
        int which = t >> 15;
        int i = t & 32767;
        int n = i >> 7, kp = i & 127;
        const float* W = which ? W2 : W1;
        float x0 = __ldg(&W[(2 * kp) * 256 + n]);
        float x1 = __ldg(&W[(2 * kp + 1) * 256 + n]);
        __half2 hp = __floats2half2_rn(x0, x1);
        unsigned hv = *reinterpret_cast<unsigned*>(&hp);
        if (which) g_W2[n * 128 + kp] = hv;
        else       g_W1[n * 128 + kp] = hv;
    } else if (t < 2 * 256 * 128 + 40 * 128) {
        int i = t - 2 * 256 * 128;
        int n = i >> 7, kp = i & 127;
        float x0 = __ldg(&W3[(2 * kp) * 40 + n]);
        float x1 = __ldg(&W3[(2 * kp + 1) * 40 + n]);
        __half2 hp = __floats2half2_rn(x0, x1);
        g_W3[n * 128 + kp] = *reinterpret_cast<unsigned*>(&hp);
    }
}

// -------- setup + dtype detect --------
__global__ void setup_kernel(const void* __restrict__ ei) {
    int i = blockIdx.x * blockDim.x + threadIdx.x;
    if (i < NNODES) { g_deg[i] = 0; g_off[i] = 0; }
    if (blockIdx.x == 0 && threadIdx.x < 256) {
        const int* w = (const int*)ei;
        if (w[2 * threadIdx.x + 1] != 0) atomicOr(&g_not64, 1);
    }
}

__device__ __forceinline__ int edge_at(const void* ei, int idx) {
    if (g_not64 == 0) return (int)((const long long*)ei)[idx];
    return ((const int*)ei)[idx];
}

__global__ void count_deg_kernel(const void* __restrict__ ei) {
    int e = blockIdx.x * blockDim.x + threadIdx.x;
    if (e < NEDGES) {
        int d = edge_at(ei, NEDGES + e);
        if ((unsigned)d < NNODES) atomicAdd(&g_deg[d], 1);
    }
}

// -------- multiblock scan --------
__global__ void scan_phaseA() {
    int i = blockIdx.x * 1024 + threadIdx.x;
    int v = (i < NNODES) ? g_deg[i] : 0;
    int s = v;
#pragma unroll
    for (int o = 16; o > 0; o >>= 1) s += __shfl_xor_sync(0xFFFFFFFFu, s, o);
    __shared__ int ws[32];
    int w = threadIdx.x >> 5, l = threadIdx.x & 31;
    if (l == 0) ws[w] = s;
    __syncthreads();
    if (w == 0) {
        int t = ws[l];
#pragma unroll
        for (int o = 16; o > 0; o >>= 1) t += __shfl_xor_sync(0xFFFFFFFFu, t, o);
        if (l == 0) g_bsum[blockIdx.x] = t;
    }
}

__global__ void scan_phaseC() {
    int i = blockIdx.x * 1024 + threadIdx.x;
    int v = (i < NNODES) ? g_deg[i] : 0;
    int w = threadIdx.x >> 5, l = threadIdx.x & 31;
    int x = v;
#pragma unroll
    for (int o = 1; o < 32; o <<= 1) {
        int y = __shfl_up_sync(0xFFFFFFFFu, x, o);
        if (l >= o) x += y;
    }
    __shared__ int wtot[32];
    __shared__ int sboff;
    if (l == 31) wtot[w] = x;
    __syncthreads();
    if (w == 0) {
        int s = 0;
        for (int b = l; b < blockIdx.x; b += 32) s += g_bsum[b];
#pragma unroll
        for (int o = 16; o > 0; o >>= 1) s += __shfl_xor_sync(0xFFFFFFFFu, s, o);
        if (l == 0) sboff = s;
        int t = wtot[l];
#pragma unroll
        for (int o = 1; o < 32; o <<= 1) {
            int y = __shfl_up_sync(0xFFFFFFFFu, t, o);
            if (l >= o) t += y;
        }
        wtot[l] = t;
    }
    __syncthreads();
    int woff = (w > 0) ? wtot[w - 1] : 0;
    int excl = sboff + woff + x - v;
    if (i < NNODES) g_rowptr[i] = excl;
    if (i == NNODES - 1) g_rowptr[NNODES] = excl + v;
}

__global__ void fill_kernel(const void* __restrict__ ei) {
    int e = blockIdx.x * blockDim.x + threadIdx.x;
    if (e < NEDGES) {
        int s = edge_at(ei, e);
        int d = edge_at(ei, NEDGES + e);
        if ((unsigned)s < NNODES && (unsigned)d < NNODES) {
            int pos = g_rowptr[d] + atomicAdd(&g_off[d], 1);
            if ((unsigned)pos < NEDGES) g_col[pos] = s;
        }
    }
}

// -------- agg (g_bufT fp16 -> g_bufA fp16) with fused bias + relu --------
__global__ void aggBR_kernel(const float* __restrict__ bias) {
    int t = blockIdx.x * blockDim.x + threadIdx.x;
    int v = t >> 6;
    int f = t & 63;
    if (v >= NNODES) return;
    const uint2* in = (const uint2*)g_bufT;
    int s = __ldg(&g_rowptr[v]);
    int e = __ldg(&g_rowptr[v + 1]);
    float4 a0 = make_float4(0.f, 0.f, 0.f, 0.f);
    float4 a1 = a0, a2 = a0, a3 = a0;
    int j = s;
    for (; j + 4 <= e; j += 4) {
        int c0 = __ldg(&g_col[j]);
        int c1 = __ldg(&g_col[j + 1]);
        int c2 = __ldg(&g_col[j + 2]);
        int c3 = __ldg(&g_col[j + 3]);
        uint2 x0 = __ldg(&in[(size_t)c0 * 64 + f]);
        uint2 x1 = __ldg(&in[(size_t)c1 * 64 + f]);
        uint2 x2 = __ldg(&in[(size_t)c2 * 64 + f]);
        uint2 x3 = __ldg(&in[(size_t)c3 * 64 + f]);
        float2 p, q;
        p = __half22float2(*(__half2*)&x0.x); q = __half22float2(*(__half2*)&x0.y);
        a0.x += p.x; a0.y += p.y; a0.z += q.x; a0.w += q.y;
        p = __half22float2(*(__half2*)&x1.x); q = __half22float2(*(__half2*)&x1.y);
        a1.x += p.x; a1.y += p.y; a1.z += q.x; a1.w += q.y;
        p = __half22float2(*(__half2*)&x2.x); q = __half22float2(*(__half2*)&x2.y);
        a2.x += p.x; a2.y += p.y; a2.z += q.x; a2.w += q.y;
        p = __half22float2(*(__half2*)&x3.x); q = __half22float2(*(__half2*)&x3.y);
        a3.x += p.x; a3.y += p.y; a3.z += q.x; a3.w += q.y;
    }
    for (; j < e; j++) {
        int c = __ldg(&g_col[j]);
        uint2 x = __ldg(&in[(size_t)c * 64 + f]);
        float2 p = __half22float2(*(__half2*)&x.x);
        float2 q = __half22float2(*(__half2*)&x.y);
        a0.x += p.x; a0.y += p.y; a0.z += q.x; a0.w += q.y;
    }
    float4 b = __ldg(&((const float4*)bias)[f]);
    float rx = fmaxf((a0.x + a1.x) + (a2.x + a3.x) + b.x, 0.f);
    float ry = fmaxf((a0.y + a1.y) + (a2.y + a3.y) + b.y, 0.f);
    float rz = fmaxf((a0.z + a1.z) + (a2.z + a3.z) + b.z, 0.f);
    float rw = fmaxf((a0.w + a1.w) + (a2.w + a3.w) + b.w, 0.f);
    __half2 h0 = __floats2half2_rn(rx, ry);
    __half2 h1 = __floats2half2_rn(rz, rw);
    uint2 st;
    st.x = *reinterpret_cast<unsigned*>(&h0);
    st.y = *reinterpret_cast<unsigned*>(&h1);
    ((uint2*)g_bufA)[(size_t)v * 64 + f] = st;
}

// -------- single-term fp16 GEMM with ldmatrix + double-buffered smem --------
#define MMA_F16(d, a, b) \
    asm volatile("mma.sync.aligned.m16n8k16.row.col.f32.f16.f16.f32 " \
        "{%0,%1,%2,%3}, {%4,%5,%6,%7}, {%8,%9}, {%0,%1,%2,%3};" \
        : "+f"(d[0]), "+f"(d[1]), "+f"(d[2]), "+f"(d[3]) \
        : "r"(a[0]), "r"(a[1]), "r"(a[2]), "r"(a[3]), "r"(b[0]), "r"(b[1]))

#define LDSM4(r0, r1, r2, r3, addr) \
    asm volatile("ldmatrix.sync.aligned.m8n8.x4.shared.b16 {%0,%1,%2,%3}, [%4];" \
        : "=r"(r0), "=r"(r1), "=r"(r2), "=r"(r3) : "r"(addr))

#define A_BUF_BYTES (64 * 12 * 4)
#define B_BUF_BYTES (128 * 12 * 4)

template<int LAYER>
__global__ void __launch_bounds__(256, 3)
gemm_f16_kernel(const float* __restrict__ Aext, int M) {
    __shared__ unsigned sA[2][64][12];    // [buf][m][kpair] fp16x2
    __shared__ unsigned sB[2][128][12];   // [buf][n][kpair] fp16x2
    const unsigned* W = (LAYER == 1) ? g_W1 : g_W2;

    const int m0 = blockIdx.x * 64;
    const int n0 = blockIdx.y * 128;
    const int tid = threadIdx.x;
    const int warp = tid >> 5, lane = tid & 31;
    const int wm = warp >> 2, wn = warp & 3;     // 2 x 4 warps
    const int g = lane >> 2, l = lane & 3;

    const int ar = tid >> 2;            // A row 0..63
    const int ac = (tid & 3) * 4;       // A k element offset
    const int akp = ac >> 1;            // pair offset 0/2/4/6
    const int bn = tid >> 1;            // B n row 0..127
    const int bq = (tid & 1) * 4;       // B kpair offset 0/4

    const int a_row = wm * 32 + (lane & 15);
    const int a_col = (lane >> 4) * 4;
    const int b_row = wn * 32 + ((lane >> 4) << 3) + (lane & 7);
    const int b_col = ((lane >> 3) & 1) * 4;
    const unsigned aA = (unsigned)__cvta_generic_to_shared(&sA[0][a_row][a_col]);
    const unsigned aB = (unsigned)__cvta_generic_to_shared(&sB[0][b_row][b_col]);

    float acc[2][4][4];
#pragma unroll
    for (int i = 0; i < 2; i++)
#pragma unroll
        for (int j = 0; j < 4; j++)
#pragma unroll
            for (int q = 0; q < 4; q++) acc[i][j][q] = 0.f;

    const bool aval = (m0 + ar) < M;
    const float*  ArowF = Aext + (size_t)(m0 + ar) * 256;
    const __half* ArowH = g_bufA + (size_t)(m0 + ar) * 256;
    const unsigned* WRow = W + (size_t)(n0 + bn) * 128;

    uint2 ha = make_uint2(0u, 0u);
    if (aval) {
        if (LAYER == 1) {
            float4 fa = *(const float4*)&ArowF[ac];
            __half2 h0 = __floats2half2_rn(fa.x, fa.y);
            __half2 h1 = __floats2half2_rn(fa.z, fa.w);
            ha.x = *reinterpret_cast<unsigned*>(&h0);
            ha.y = *reinterpret_cast<unsigned*>(&h1);
        } else {
            ha = *(const uint2*)&ArowH[ac];
        }
    }
    uint4 wv = *(const uint4*)&WRow[bq];

    int p = 0;
#pragma unroll 1
    for (int kt = 0; kt < 16; kt++) {
        *(uint2*)&sA[p][ar][akp] = ha;
        *(uint4*)&sB[p][bn][bq] = wv;
        __syncthreads();
        if (kt < 15) {
            int k = (kt + 1) * 16;
            ha = make_uint2(0u, 0u);
            if (aval) {
                if (LAYER == 1) {
                    float4 fa = *(const float4*)&ArowF[k + ac];
                    __half2 h0 = __floats2half2_rn(fa.x, fa.y);
                    __half2 h1 = __floats2half2_rn(fa.z, fa.w);
                    ha.x = *reinterpret_cast<unsigned*>(&h0);
                    ha.y = *reinterpret_cast<unsigned*>(&h1);
                } else {
                    ha = *(const uint2*)&ArowH[k + ac];
                }
            }
            wv = *(const uint4*)&WRow[(kt + 1) * 8 + bq];
        }
        const unsigned offA = (unsigned)(p * A_BUF_BYTES);
        const unsigned offB = (unsigned)(p * B_BUF_BYTES);
        unsigned ah[2][4], bh[4][2];
        LDSM4(ah[0][0], ah[0][1], ah[0][2], ah[0][3], aA + offA);
        LDSM4(ah[1][0], ah[1][1], ah[1][2], ah[1][3], aA + offA + 16 * 48);
        LDSM4(bh[0][0], bh[0][1], bh[1][0], bh[1][1], aB + offB);
        LDSM4(bh[2][0], bh[2][1], bh[3][0], bh[3][1], aB + offB + 16 * 48);
#pragma unroll
        for (int i = 0; i < 2; i++)
#pragma unroll
            for (int j = 0; j < 4; j++)
                MMA_F16(acc[i][j], ah[i], bh[j]);
        p ^= 1;
    }

#pragma unroll
    for (int i = 0; i < 2; i++) {
        int row0 = m0 + wm * 32 + i * 16 + g;
        int row1 = row0 + 8;
#pragma unroll
        for (int j = 0; j < 4; j++) {
            int col = n0 + wn * 32 + j * 8 + 2 * l;
            if (row0 < M) {
                __half2 v = __floats2half2_rn(acc[i][j][0], acc[i][j][1]);
                *(__half2*)&g_bufT[(size_t)row0 * 256 + col] = v;
            }
            if (row1 < M) {
                __half2 v = __floats2half2_rn(acc[i][j][2], acc[i][j][3]);
                *(__half2*)&g_bufT[(size_t)row1 * 256 + col] = v;
            }
        }
    }
}

// -------- layer-3 projection (fp16 MMA): g_P = g_bufA(fp16) @ W3 --------
// Block = 128 rows, 8 warps x m16, all 40 cols (5 n8-tiles), k-step 16.
// Fragment register layouts verified by R6 (A scalar) and R9 (B scalar) runs.
__global__ void __launch_bounds__(256, 2)
gemm3_kernel(int M) {
    __shared__ unsigned sA[2][128][12];    // [buf][m][kpair]
    __shared__ unsigned sW3[40][132];      // [n][kpair], pad 132 (conflict-free)
    const int m0 = blockIdx.x * 128;
    const int tid = threadIdx.x;
    const int warp = tid >> 5, lane = tid & 31;
    const int g = lane >> 2, l = lane & 3;

    // load full W3 image into smem
    for (int i = tid; i < 40 * 128; i += 256)
        sW3[i >> 7][i & 127] = g_W3[i];

    const int ar = tid >> 1;              // A row 0..127
    const int aq = (tid & 1) * 4;         // kpair offset 0/4 (uint4 = 4 kpairs)
    const bool aval = (m0 + ar) < M;
    const __half* Arow = g_bufA + (size_t)(m0 + ar) * 256;

    float acc[5][4];
#pragma unroll
    for (int j = 0; j < 5; j++)
#pragma unroll
        for (int q = 0; q < 4; q++) acc[j][q] = 0.f;

    uint4 ha = make_uint4(0u, 0u, 0u, 0u);
    if (aval) ha = *(const uint4*)&Arow[aq * 2];

    const int r0 = warp * 16 + g;
    const int r1 = r0 + 8;

    int p = 0;
#pragma unroll 1
    for (int kt = 0; kt < 16; kt++) {
        *(uint4*)&sA[p][ar][aq] = ha;
        __syncthreads();
        if (kt < 15) {
            ha = make_uint4(0u, 0u, 0u, 0u);
            if (aval) ha = *(const uint4*)&Arow[(kt + 1) * 16 + aq * 2];
        }
        unsigned a[4];
        a[0] = sA[p][r0][l];
        a[1] = sA[p][r1][l];
        a[2] = sA[p][r0][l + 4];
        a[3] = sA[p][r1][l + 4];
#pragma unroll
        for (int j = 0; j < 5; j++) {
            unsigned b[2];
            b[0] = sW3[j * 8 + g][kt * 8 + l];
            b[1] = sW3[j * 8 + g][kt * 8 + l + 4];
            MMA_F16(acc[j], a, b);
        }
        p ^= 1;
    }

    int row0 = m0 + warp * 16 + g;
    int row1 = row0 + 8;
#pragma unroll
    for (int j = 0; j < 5; j++) {
        int col = j * 8 + 2 * l;
        if (row0 < M) {
            g_P[(size_t)row0 * NCLS + col] = acc[j][0];
            g_P[(size_t)row0 * NCLS + col + 1] = acc[j][1];
        }
        if (row1 < M) {
            g_P[(size_t)row1 * NCLS + col] = acc[j][2];
            g_P[(size_t)row1 * NCLS + col + 1] = acc[j][3];
        }
    }
}

// -------- final: out[v] = log_softmax( agg(P)[v] + b3 ); warp per node --------
__global__ void aggout_kernel(const float* __restrict__ b3, float* __restrict__ out, int M) {
    int warp = (blockIdx.x * blockDim.x + threadIdx.x) >> 5;
    int lane = threadIdx.x & 31;
    if (warp >= M) return;
    int s = __ldg(&g_rowptr[warp]);
    int e = __ldg(&g_rowptr[warp + 1]);
    bool act = lane < 20;
    int c0 = lane, c1 = lane + 20;
    float acc0 = 0.f, acc1 = 0.f;
    for (int j = s; j < e; j++) {
        int c = __ldg(&g_col[j]);
        const float* pr = &g_P[(size_t)c * NCLS];
        if (act) {
            acc0 += pr[c0];
            acc1 += pr[c1];
        }
    }
    float v0 = act ? acc0 + __ldg(&b3[c0]) : -INFINITY;
    float v1 = act ? acc1 + __ldg(&b3[c1]) : -INFINITY;
    float m = fmaxf(v0, v1);
#pragma unroll
    for (int o = 16; o > 0; o >>= 1) m = fmaxf(m, __shfl_xor_sync(0xFFFFFFFFu, m, o));
    float ssum = act ? (expf(v0 - m) + expf(v1 - m)) : 0.f;
#pragma unroll
    for (int o = 16; o > 0; o >>= 1) ssum += __shfl_xor_sync(0xFFFFFFFFu, ssum, o);
    float ls = logf(ssum);
    if (act) {
        out[(size_t)warp * NCLS + c0] = v0 - m - ls;
        out[(size_t)warp * NCLS + c1] = v1 - m - ls;
    }
}

__global__ void tail_kernel(float* out, int start, int total, float val) {
    int i = start + blockIdx.x * blockDim.x + threadIdx.x;
    if (i < total) out[i] = val;
}

extern "C" void kernel_launch(void* const* d_in, const int* in_sizes, int n_in,
                              void* d_out, int out_size) {
    const float* features = (const float*)d_in[0];
    const void*  ei       = d_in[1];
    const float* W1 = (const float*)d_in[4];
    const float* b1 = (const float*)d_in[5];
    const float* W2 = (const float*)d_in[6];
    const float* b2 = (const float*)d_in[7];
    const float* W3 = (const float*)d_in[8];
    const float* b3 = (const float*)d_in[9];
    float* out = (float*)d_out;

    const int N = NNODES, E = NEDGES;
    dim3 ggrid((N + 63) / 64, 2);

    // fork/join: CSR build + tail on side stream, overlapped with prepW+gemm1
    cudaStream_t s2;
    cudaStreamCreateWithFlags(&s2, cudaStreamNonBlocking);
    cudaEvent_t evFork, evJoin;
    cudaEventCreateWithFlags(&evFork, cudaEventDisableTiming);
    cudaEventCreateWithFlags(&evJoin, cudaEventDisableTiming);

    cudaEventRecord(evFork, 0);
    cudaStreamWaitEvent(s2, evFork, 0);

    // side stream: CSR chain + output tail
    setup_kernel<<<(N + 255) / 256, 256, 0, s2>>>(ei);
    count_deg_kernel<<<(E + 255) / 256, 256, 0, s2>>>(ei);
    scan_phaseA<<<SCAN_BLOCKS, 1024, 0, s2>>>();
    scan_phaseC<<<SCAN_BLOCKS, 1024, 0, s2>>>();
    fill_kernel<<<(E + 255) / 256, 256, 0, s2>>>(ei);
    int NC = N * NCLS;
    if (out_size > NC) {
        int extra = out_size - NC;
        tail_kernel<<<(extra + 255) / 256, 256, 0, s2>>>(out, NC, out_size, (float)(3 * N));
    }
    cudaEventRecord(evJoin, s2);

    // main stream: weights prep + layer-1 GEMM (independent of CSR)
    prepW_kernel<<<(2 * 256 * 128 + 40 * 128 + 255) / 256, 256>>>(W1, W2, W3);
    gemm_f16_kernel<1><<<ggrid, 256>>>(features, N);           // T1 = X@W1

    // join: aggregation needs CSR
    cudaStreamWaitEvent(0, evJoin, 0);
    aggBR_kernel<<<(N * 64 + 255) / 256, 256>>>(b1);           // H1 = relu(agg(T1)+b1)
    gemm_f16_kernel<2><<<ggrid, 256>>>(features, N);           // T2 = H1@W2
    aggBR_kernel<<<(N * 64 + 255) / 256, 256>>>(b2);           // H2 = relu(agg(T2)+b2)
    gemm3_kernel<<<(N + 127) / 128, 256>>>(N);                 // P = H2@W3
    aggout_kernel<<<(N * 32 + 255) / 256, 256>>>(b3, out, N);
}

// round 17
// speedup vs baseline: 1.8970x; 1.0028x over previous
#include <cuda_runtime.h>
#include <cuda_fp16.h>
#include <cstdint>
#include <math.h>

#define NNODES 50000
#define NEDGES 800000
#define FDIM   256
#define NCLS   40
#define SCAN_BLOCKS ((NNODES + 1023) / 1024)

// -------- scratch --------
__device__ __half g_bufA[(size_t)(NNODES + 64) * FDIM];   // H (post-agg, fp16)
__device__ __half g_bufT[(size_t)(NNODES + 64) * FDIM];   // T = A@W (pre-agg, fp16)
__device__ float  g_P[(size_t)NNODES * NCLS];
__device__ unsigned g_W1[256 * 128], g_W2[256 * 128];     // [n][kpair] packed fp16x2
__device__ unsigned g_W3[40 * 128];                       // [n][kpair] packed fp16x2
__device__ int   g_deg[NNODES];
__device__ int   g_off[NNODES];
__device__ int   g_rowptr[NNODES + 1];
__device__ int   g_col[NEDGES];
__device__ int   g_bsum[SCAN_BLOCKS];
__device__ int   g_not64 = 0;

// -------- W prep: fp16 [n][kpair] for W1, W2, W3 --------
__global__ void prepW_kernel(const float* __restrict__ W1, const float* __restrict__ W2,
                             const float* __restrict__ W3) {
    int t = blockIdx.x * blockDim.x + threadIdx.x;
    if (t < 2 * 256 * 128) {
        int which = t >> 15;
        int i = t & 32767;
        int n = i >> 7, kp = i & 127;
        const float* W = which ? W2 : W1;
        float x0 = __ldg(&W[(2 * kp) * 256 + n]);
        float x1 = __ldg(&W[(2 * kp + 1) * 256 + n]);
        __half2 hp = __floats2half2_rn(x0, x1);
        unsigned hv = *reinterpret_cast<unsigned*>(&hp);
        if (which) g_W2[n * 128 + kp] = hv;
        else       g_W1[n * 128 + kp] = hv;
    } else if (t < 2 * 256 * 128 + 40 * 128) {
        int i = t - 2 * 256 * 128;
        int n = i >> 7, kp = i & 127;
        float x0 = __ldg(&W3[(2 * kp) * 40 + n]);
        float x1 = __ldg(&W3[(2 * kp + 1) * 40 + n]);
        __half2 hp = __floats2half2_rn(x0, x1);
        g_W3[n * 128 + kp] = *reinterpret_cast<unsigned*>(&hp);
    }
}

// -------- setup + dtype detect --------
__global__ void setup_kernel(const void* __restrict__ ei) {
    int i = blockIdx.x * blockDim.x + threadIdx.x;
    if (i < NNODES) { g_deg[i] = 0; g_off[i] = 0; }
    if (blockIdx.x == 0 && threadIdx.x < 256) {
        const int* w = (const int*)ei;
        if (w[2 * threadIdx.x + 1] != 0) atomicOr(&g_not64, 1);
    }
}

__device__ __forceinline__ int edge_at(const void* ei, int idx) {
    if (g_not64 == 0) return (int)((const long long*)ei)[idx];
    return ((const int*)ei)[idx];
}

__global__ void count_deg_kernel(const void* __restrict__ ei) {
    int e = blockIdx.x * blockDim.x + threadIdx.x;
    if (e < NEDGES) {
        int d = edge_at(ei, NEDGES + e);
        if ((unsigned)d < NNODES) atomicAdd(&g_deg[d], 1);
    }
}

// -------- multiblock scan --------
__global__ void scan_phaseA() {
    int i = blockIdx.x * 1024 + threadIdx.x;
    int v = (i < NNODES) ? g_deg[i] : 0;
    int s = v;
#pragma unroll
    for (int o = 16; o > 0; o >>= 1) s += __shfl_xor_sync(0xFFFFFFFFu, s, o);
    __shared__ int ws[32];
    int w = threadIdx.x >> 5, l = threadIdx.x & 31;
    if (l == 0) ws[w] = s;
    __syncthreads();
    if (w == 0) {
        int t = ws[l];
#pragma unroll
        for (int o = 16; o > 0; o >>= 1) t += __shfl_xor_sync(0xFFFFFFFFu, t, o);
        if (l == 0) g_bsum[blockIdx.x] = t;
    }
}

__global__ void scan_phaseC() {
    int i = blockIdx.x * 1024 + threadIdx.x;
    int v = (i < NNODES) ? g_deg[i] : 0;
    int w = threadIdx.x >> 5, l = threadIdx.x & 31;
    int x = v;
#pragma unroll
    for (int o = 1; o < 32; o <<= 1) {
        int y = __shfl_up_sync(0xFFFFFFFFu, x, o);
        if (l >= o) x += y;
    }
    __shared__ int wtot[32];
    __shared__ int sboff;
    if (l == 31) wtot[w] = x;
    __syncthreads();
    if (w == 0) {
        int s = 0;
        for (int b = l; b < blockIdx.x; b += 32) s += g_bsum[b];
#pragma unroll
        for (int o = 16; o > 0; o >>= 1) s += __shfl_xor_sync(0xFFFFFFFFu, s, o);
        if (l == 0) sboff = s;
        int t = wtot[l];
#pragma unroll
        for (int o = 1; o < 32; o <<= 1) {
            int y = __shfl_up_sync(0xFFFFFFFFu, t, o);
            if (l >= o) t += y;
        }
        wtot[l] = t;
    }
    __syncthreads();
    int woff = (w > 0) ? wtot[w - 1] : 0;
    int excl = sboff + woff + x - v;
    if (i < NNODES) g_rowptr[i] = excl;
    if (i == NNODES - 1) g_rowptr[NNODES] = excl + v;
}

__global__ void fill_kernel(const void* __restrict__ ei) {
    int e = blockIdx.x * blockDim.x + threadIdx.x;
    if (e < NEDGES) {
        int s = edge_at(ei, e);
        int d = edge_at(ei, NEDGES + e);
        if ((unsigned)s < NNODES && (unsigned)d < NNODES) {
            int pos = g_rowptr[d] + atomicAdd(&g_off[d], 1);
            if ((unsigned)pos < NEDGES) g_col[pos] = s;
        }
    }
}

// -------- agg (g_bufT fp16 -> g_bufA fp16) with fused bias + relu --------
__global__ void aggBR_kernel(const float* __restrict__ bias) {
    int t = blockIdx.x * blockDim.x + threadIdx.x;
    int v = t >> 6;
    int f = t & 63;
    if (v >= NNODES) return;
    const uint2* in = (const uint2*)g_bufT;
    int s = __ldg(&g_rowptr[v]);
    int e = __ldg(&g_rowptr[v + 1]);
    float4 a0 = make_float4(0.f, 0.f, 0.f, 0.f);
    float4 a1 = a0, a2 = a0, a3 = a0;
    int j = s;
    for (; j + 4 <= e; j += 4) {
        int c0 = __ldg(&g_col[j]);
        int c1 = __ldg(&g_col[j + 1]);
        int c2 = __ldg(&g_col[j + 2]);
        int c3 = __ldg(&g_col[j + 3]);
        uint2 x0 = __ldg(&in[(size_t)c0 * 64 + f]);
        uint2 x1 = __ldg(&in[(size_t)c1 * 64 + f]);
        uint2 x2 = __ldg(&in[(size_t)c2 * 64 + f]);
        uint2 x3 = __ldg(&in[(size_t)c3 * 64 + f]);
        float2 p, q;
        p = __half22float2(*(__half2*)&x0.x); q = __half22float2(*(__half2*)&x0.y);
        a0.x += p.x; a0.y += p.y; a0.z += q.x; a0.w += q.y;
        p = __half22float2(*(__half2*)&x1.x); q = __half22float2(*(__half2*)&x1.y);
        a1.x += p.x; a1.y += p.y; a1.z += q.x; a1.w += q.y;
        p = __half22float2(*(__half2*)&x2.x); q = __half22float2(*(__half2*)&x2.y);
        a2.x += p.x; a2.y += p.y; a2.z += q.x; a2.w += q.y;
        p = __half22float2(*(__half2*)&x3.x); q = __half22float2(*(__half2*)&x3.y);
        a3.x += p.x; a3.y += p.y; a3.z += q.x; a3.w += q.y;
    }
    for (; j < e; j++) {
        int c = __ldg(&g_col[j]);
        uint2 x = __ldg(&in[(size_t)c * 64 + f]);
        float2 p = __half22float2(*(__half2*)&x.x);
        float2 q = __half22float2(*(__half2*)&x.y);
        a0.x += p.x; a0.y += p.y; a0.z += q.x; a0.w += q.y;
    }
    float4 b = __ldg(&((const float4*)bias)[f]);
    float rx = fmaxf((a0.x + a1.x) + (a2.x + a3.x) + b.x, 0.f);
    float ry = fmaxf((a0.y + a1.y) + (a2.y + a3.y) + b.y, 0.f);
    float rz = fmaxf((a0.z + a1.z) + (a2.z + a3.z) + b.z, 0.f);
    float rw = fmaxf((a0.w + a1.w) + (a2.w + a3.w) + b.w, 0.f);
    __half2 h0 = __floats2half2_rn(rx, ry);
    __half2 h1 = __floats2half2_rn(rz, rw);
    uint2 st;
    st.x = *reinterpret_cast<unsigned*>(&h0);
    st.y = *reinterpret_cast<unsigned*>(&h1);
    ((uint2*)g_bufA)[(size_t)v * 64 + f] = st;
}

// -------- single-term fp16 GEMM with ldmatrix + double-buffered smem --------
#define MMA_F16(d, a, b) \
    asm volatile("mma.sync.aligned.m16n8k16.row.col.f32.f16.f16.f32 " \
        "{%0,%1,%2,%3}, {%4,%5,%6,%7}, {%8,%9}, {%0,%1,%2,%3};" \
        : "+f"(d[0]), "+f"(d[1]), "+f"(d[2]), "+f"(d[3]) \
        : "r"(a[0]), "r"(a[1]), "r"(a[2]), "r"(a[3]), "r"(b[0]), "r"(b[1]))

#define LDSM4(r0, r1, r2, r3, addr) \
    asm volatile("ldmatrix.sync.aligned.m8n8.x4.shared.b16 {%0,%1,%2,%3}, [%4];" \
        : "=r"(r0), "=r"(r1), "=r"(r2), "=r"(r3) : "r"(addr))

#define A_BUF_BYTES (64 * 12 * 4)
#define B_BUF_BYTES (128 * 12 * 4)

template<int LAYER>
__global__ void __launch_bounds__(256, 3)
gemm_f16_kernel(const float* __restrict__ Aext, int M) {
    __shared__ unsigned sA[2][64][12];    // [buf][m][kpair] fp16x2
    __shared__ unsigned sB[2][128][12];   // [buf][n][kpair] fp16x2
    const unsigned* W = (LAYER == 1) ? g_W1 : g_W2;

    const int m0 = blockIdx.x * 64;
    const int n0 = blockIdx.y * 128;
    const int tid = threadIdx.x;
    const int warp = tid >> 5, lane = tid & 31;
    const int wm = warp >> 2, wn = warp & 3;     // 2 x 4 warps
    const int g = lane >> 2, l = lane & 3;

    const int ar = tid >> 2;            // A row 0..63
    const int ac = (tid & 3) * 4;       // A k element offset
    const int akp = ac >> 1;            // pair offset 0/2/4/6
    const int bn = tid >> 1;            // B n row 0..127
    const int bq = (tid & 1) * 4;       // B kpair offset 0/4

    const int a_row = wm * 32 + (lane & 15);
    const int a_col = (lane >> 4) * 4;
    const int b_row = wn * 32 + ((lane >> 4) << 3) + (lane & 7);
    const int b_col = ((lane >> 3) & 1) * 4;
    const unsigned aA = (unsigned)__cvta_generic_to_shared(&sA[0][a_row][a_col]);
    const unsigned aB = (unsigned)__cvta_generic_to_shared(&sB[0][b_row][b_col]);

    float acc[2][4][4];
#pragma unroll
    for (int i = 0; i < 2; i++)
#pragma unroll
        for (int j = 0; j < 4; j++)
#pragma unroll
            for (int q = 0; q < 4; q++) acc[i][j][q] = 0.f;

    const bool aval = (m0 + ar) < M;
    const float*  ArowF = Aext + (size_t)(m0 + ar) * 256;
    const __half* ArowH = g_bufA + (size_t)(m0 + ar) * 256;
    const unsigned* WRow = W + (size_t)(n0 + bn) * 128;

    uint2 ha = make_uint2(0u, 0u);
    if (aval) {
        if (LAYER == 1) {
            float4 fa = *(const float4*)&ArowF[ac];
            __half2 h0 = __floats2half2_rn(fa.x, fa.y);
            __half2 h1 = __floats2half2_rn(fa.z, fa.w);
            ha.x = *reinterpret_cast<unsigned*>(&h0);
            ha.y = *reinterpret_cast<unsigned*>(&h1);
        } else {
            ha = *(const uint2*)&ArowH[ac];
        }
    }
    uint4 wv = *(const uint4*)&WRow[bq];

    int p = 0;
#pragma unroll 1
    for (int kt = 0; kt < 16; kt++) {
        *(uint2*)&sA[p][ar][akp] = ha;
        *(uint4*)&sB[p][bn][bq] = wv;
        __syncthreads();
        if (kt < 15) {
            int k = (kt + 1) * 16;
            ha = make_uint2(0u, 0u);
            if (aval) {
                if (LAYER == 1) {
                    float4 fa = *(const float4*)&ArowF[k + ac];
                    __half2 h0 = __floats2half2_rn(fa.x, fa.y);
                    __half2 h1 = __floats2half2_rn(fa.z, fa.w);
                    ha.x = *reinterpret_cast<unsigned*>(&h0);
                    ha.y = *reinterpret_cast<unsigned*>(&h1);
                } else {
                    ha = *(const uint2*)&ArowH[k + ac];
                }
            }
            wv = *(const uint4*)&WRow[(kt + 1) * 8 + bq];
        }
        const unsigned offA = (unsigned)(p * A_BUF_BYTES);
        const unsigned offB = (unsigned)(p * B_BUF_BYTES);
        unsigned ah[2][4], bh[4][2];
        LDSM4(ah[0][0], ah[0][1], ah[0][2], ah[0][3], aA + offA);
        LDSM4(ah[1][0], ah[1][1], ah[1][2], ah[1][3], aA + offA + 16 * 48);
        LDSM4(bh[0][0], bh[0][1], bh[1][0], bh[1][1], aB + offB);
        LDSM4(bh[2][0], bh[2][1], bh[3][0], bh[3][1], aB + offB + 16 * 48);
#pragma unroll
        for (int i = 0; i < 2; i++)
#pragma unroll
            for (int j = 0; j < 4; j++)
                MMA_F16(acc[i][j], ah[i], bh[j]);
        p ^= 1;
    }

#pragma unroll
    for (int i = 0; i < 2; i++) {
        int row0 = m0 + wm * 32 + i * 16 + g;
        int row1 = row0 + 8;
#pragma unroll
        for (int j = 0; j < 4; j++) {
            int col = n0 + wn * 32 + j * 8 + 2 * l;
            if (row0 < M) {
                __half2 v = __floats2half2_rn(acc[i][j][0], acc[i][j][1]);
                *(__half2*)&g_bufT[(size_t)row0 * 256 + col] = v;
            }
            if (row1 < M) {
                __half2 v = __floats2half2_rn(acc[i][j][2], acc[i][j][3]);
                *(__half2*)&g_bufT[(size_t)row1 * 256 + col] = v;
            }
        }
    }
}

// -------- layer-3 projection (fp16 MMA): g_P = g_bufA(fp16) @ W3 --------
// Block = 128 rows, 8 warps x m16, all 40 cols (5 n8-tiles), k-step 16.
// Fragment register layouts verified by R6 (A scalar) and R9 (B scalar) runs.
__global__ void __launch_bounds__(256, 2)
gemm3_kernel(int M) {
    __shared__ unsigned sA[2][128][12];    // [buf][m][kpair]
    __shared__ unsigned sW3[40][132];      // [n][kpair], pad 132 (conflict-free)
    const int m0 = blockIdx.x * 128;
    const int tid = threadIdx.x;
    const int warp = tid >> 5, lane = tid & 31;
    const int g = lane >> 2, l = lane & 3;

    // load full W3 image into smem
    for (int i = tid; i < 40 * 128; i += 256)
        sW3[i >> 7][i & 127] = g_W3[i];

    const int ar = tid >> 1;              // A row 0..127
    const int aq = (tid & 1) * 4;         // kpair offset 0/4 (uint4 = 4 kpairs)
    const bool aval = (m0 + ar) < M;
    const __half* Arow = g_bufA + (size_t)(m0 + ar) * 256;

    float acc[5][4];
#pragma unroll
    for (int j = 0; j < 5; j++)
#pragma unroll
        for (int q = 0; q < 4; q++) acc[j][q] = 0.f;

    uint4 ha = make_uint4(0u, 0u, 0u, 0u);
    if (aval) ha = *(const uint4*)&Arow[aq * 2];

    const int r0 = warp * 16 + g;
    const int r1 = r0 + 8;

    int p = 0;
#pragma unroll 1
    for (int kt = 0; kt < 16; kt++) {
        *(uint4*)&sA[p][ar][aq] = ha;
        __syncthreads();
        if (kt < 15) {
            ha = make_uint4(0u, 0u, 0u, 0u);
            if (aval) ha = *(const uint4*)&Arow[(kt + 1) * 16 + aq * 2];
        }
        unsigned a[4];
        a[0] = sA[p][r0][l];
        a[1] = sA[p][r1][l];
        a[2] = sA[p][r0][l + 4];
        a[3] = sA[p][r1][l + 4];
#pragma unroll
        for (int j = 0; j < 5; j++) {
            unsigned b[2];
            b[0] = sW3[j * 8 + g][kt * 8 + l];
            b[1] = sW3[j * 8 + g][kt * 8 + l + 4];
            MMA_F16(acc[j], a, b);
        }
        p ^= 1;
    }

    int row0 = m0 + warp * 16 + g;
    int row1 = row0 + 8;
#pragma unroll
    for (int j = 0; j < 5; j++) {
        int col = j * 8 + 2 * l;
        if (row0 < M) {
            g_P[(size_t)row0 * NCLS + col] = acc[j][0];
            g_P[(size_t)row0 * NCLS + col + 1] = acc[j][1];
        }
        if (row1 < M) {
            g_P[(size_t)row1 * NCLS + col] = acc[j][2];
            g_P[(size_t)row1 * NCLS + col + 1] = acc[j][3];
        }
    }
}

// -------- final: out[v] = log_softmax( agg(P)[v] + b3 ); warp per node --------
__global__ void aggout_kernel(const float* __restrict__ b3, float* __restrict__ out, int M) {
    int warp = (blockIdx.x * blockDim.x + threadIdx.x) >> 5;
    int lane = threadIdx.x & 31;
    if (warp >= M) return;
    int s = __ldg(&g_rowptr[warp]);
    int e = __ldg(&g_rowptr[warp + 1]);
    bool act = lane < 20;
    int c0 = lane, c1 = lane + 20;
    float acc0 = 0.f, acc1 = 0.f;
    for (int j = s; j < e; j++) {
        int c = __ldg(&g_col[j]);
        const float* pr = &g_P[(size_t)c * NCLS];
        if (act) {
            acc0 += pr[c0];
            acc1 += pr[c1];
        }
    }
    float v0 = act ? acc0 + __ldg(&b3[c0]) : -INFINITY;
    float v1 = act ? acc1 + __ldg(&b3[c1]) : -INFINITY;
    float m = fmaxf(v0, v1);
#pragma unroll
    for (int o = 16; o > 0; o >>= 1) m = fmaxf(m, __shfl_xor_sync(0xFFFFFFFFu, m, o));
    float ssum = act ? (expf(v0 - m) + expf(v1 - m)) : 0.f;
#pragma unroll
    for (int o = 16; o > 0; o >>= 1) ssum += __shfl_xor_sync(0xFFFFFFFFu, ssum, o);
    float ls = logf(ssum);
    if (act) {
        out[(size_t)warp * NCLS + c0] = v0 - m - ls;
        out[(size_t)warp * NCLS + c1] = v1 - m - ls;
    }
}

__global__ void tail_kernel(float* out, int start, int total, float val) {
    int i = start + blockIdx.x * blockDim.x + threadIdx.x;
    if (i < total) out[i] = val;
}

extern "C" void kernel_launch(void* const* d_in, const int* in_sizes, int n_in,
                              void* d_out, int out_size) {
    const float* features = (const float*)d_in[0];
    const void*  ei       = d_in[1];
    const float* W1 = (const float*)d_in[4];
    const float* b1 = (const float*)d_in[5];
    const float* W2 = (const float*)d_in[6];
    const float* b2 = (const float*)d_in[7];
    const float* W3 = (const float*)d_in[8];
    const float* b3 = (const float*)d_in[9];
    float* out = (float*)d_out;

    const int N = NNODES, E = NEDGES;
    dim3 ggrid((N + 63) / 64, 2);

    // fork/join: CSR build + tail on side stream, overlapped with prepW+gemm1
    cudaStream_t s2;
    cudaStreamCreateWithFlags(&s2, cudaStreamNonBlocking);
    cudaEvent_t evFork, evJoin;
    cudaEventCreateWithFlags(&evFork, cudaEventDisableTiming);
    cudaEventCreateWithFlags(&evJoin, cudaEventDisableTiming);

    cudaEventRecord(evFork, 0);
    cudaStreamWaitEvent(s2, evFork, 0);

    // side stream: CSR chain + output tail
    setup_kernel<<<(N + 255) / 256, 256, 0, s2>>>(ei);
    count_deg_kernel<<<(E + 255) / 256, 256, 0, s2>>>(ei);
    scan_phaseA<<<SCAN_BLOCKS, 1024, 0, s2>>>();
    scan_phaseC<<<SCAN_BLOCKS, 1024, 0, s2>>>();
    fill_kernel<<<(E + 255) / 256, 256, 0, s2>>>(ei);
    int NC = N * NCLS;
    if (out_size > NC) {
        int extra = out_size - NC;
        tail_kernel<<<(extra + 255) / 256, 256, 0, s2>>>(out, NC, out_size, (float)(3 * N));
    }
    cudaEventRecord(evJoin, s2);

    // main stream: weights prep + layer-1 GEMM (independent of CSR)
    prepW_kernel<<<(2 * 256 * 128 + 40 * 128 + 255) / 256, 256>>>(W1, W2, W3);
    gemm_f16_kernel<1><<<ggrid, 256>>>(features, N);           // T1 = X@W1

    // join: aggregation needs CSR
    cudaStreamWaitEvent(0, evJoin, 0);
    aggBR_kernel<<<(N * 64 + 255) / 256, 256>>>(b1);           // H1 = relu(agg(T1)+b1)
    gemm_f16_kernel<2><<<ggrid, 256>>>(features, N);           // T2 = H1@W2
    aggBR_kernel<<<(N * 64 + 255) / 256, 256>>>(b2);           // H2 = relu(agg(T2)+b2)
    gemm3_kernel<<<(N + 127) / 128, 256>>>(N);                 // P = H2@W3
    aggout_kernel<<<(N * 32 + 255) / 256, 256>>>(b3, out, N);
}